// round 5
// baseline (speedup 1.0000x reference)
#include <cuda_runtime.h>

#define NN   8192
#define HH   128
#define EE   131072
#define NRELC 90
#define NBC  8
#define SIC  16

// ---------------- device scratch (no allocations allowed) ----------------
__device__ float g_x0[NN*HH];
__device__ float g_h1[NN*HH];
__device__ float g_h2[NN*HH];
__device__ float g_agg[NN*HH];
__device__ float g_zml[NN*2*HH];
__device__ float g_z[NN*HH];
__device__ float g_M[NN*HH];
__device__ float g_h3[NN*HH];
__device__ float g_S[HH*HH];
__device__ int   g_perm[EE];
__device__ int   g_cnt[NRELC];
__device__ int   g_off[NRELC+1];
__device__ int   g_cur[NRELC];

// ---------------- trivial kernels ----------------
__global__ void k_zero(float* __restrict__ p, int n4) {
    int i = blockIdx.x * blockDim.x + threadIdx.x;
    if (i < n4) ((float4*)p)[i] = make_float4(0.f, 0.f, 0.f, 0.f);
}

__global__ void k_zero_cnt() {
    int i = threadIdx.x;
    if (i < NRELC) g_cnt[i] = 0;
}

__global__ void k_gather(const float* __restrict__ emb, const int* __restrict__ ids) {
    int i = blockIdx.x * blockDim.x + threadIdx.x;   // over NN*32 float4
    int row = i >> 5, c = i & 31;
    int nid = ids[row];
    ((float4*)g_x0)[i] = ((const float4*)emb)[nid * 32 + c];
}

__global__ void k_hist(const int* __restrict__ et) {
    int i = blockIdx.x * blockDim.x + threadIdx.x;
    if (i < EE) atomicAdd(&g_cnt[et[i]], 1);
}

__global__ void k_scan() {
    if (threadIdx.x == 0) {
        int acc = 0;
        for (int r = 0; r < NRELC; r++) {
            g_off[r] = acc;
            g_cur[r] = acc;
            acc += g_cnt[r];
        }
        g_off[NRELC] = acc;
    }
}

__global__ void k_permute(const int* __restrict__ et) {
    int i = blockIdx.x * blockDim.x + threadIdx.x;
    if (i < EE) {
        int p = atomicAdd(&g_cur[et[i]], 1);
        g_perm[p] = i;
    }
}

__global__ void k_z(const float* __restrict__ eps) {
    int i = blockIdx.x * blockDim.x + threadIdx.x;   // over NN*HH
    int row = i >> 7, col = i & 127;
    float m  = g_zml[row * 256 + col];
    float ls = g_zml[row * 256 + 128 + col];
    g_z[i] = m + expf(ls) * eps[i];
}

// ---------------- RGCN edge message kernel (sorted by relation) ----------------
// grid: (CHUNKS, NREL), block 256 = 8 warps, 1 warp per edge.
// Each lane computes 4 consecutive output elements (one float4 atomicAdd).
__global__ void __launch_bounds__(256) k_edge(
    const float* __restrict__ x, const float* __restrict__ W,
    const int* __restrict__ src, const int* __restrict__ dst,
    const float* __restrict__ norm, float* __restrict__ agg)
{
    __shared__ float Ws[NBC * SIC * SIC];   // 2048 floats = 8 KB
    int rel = blockIdx.y;
    int start = g_off[rel], end = g_off[rel + 1];
    if (start == end) return;

    for (int i = threadIdx.x; i < NBC * SIC * SIC; i += 256)
        Ws[i] = W[rel * NBC * SIC * SIC + i];
    __syncthreads();

    int warp = threadIdx.x >> 5, lane = threadIdx.x & 31;
    int b = lane >> 2;                    // block-diag block 0..7
    int j = (lane & 3) << 2;              // output col base within block
    const float* Wb = Ws + b * (SIC * SIC);

    for (int idx = start + blockIdx.x * 8 + warp; idx < end; idx += gridDim.x * 8) {
        int e = g_perm[idx];
        int s = src[e], d = dst[e];
        float nrm = norm[e];
        float4 xv = ((const float4*)(x + (long)s * HH))[lane];  // lane holds x[4*lane..]

        float4 acc = make_float4(0.f, 0.f, 0.f, 0.f);
        #pragma unroll
        for (int i = 0; i < SIC; i++) {
            // value x[b*16 + i] lives in lane (b*4 + i/4), component i%4
            int srcLane = (lane & 28) + (i >> 2);
            float comp;
            switch (i & 3) {
                case 0: comp = xv.x; break;
                case 1: comp = xv.y; break;
                case 2: comp = xv.z; break;
                default: comp = xv.w; break;
            }
            float xi = __shfl_sync(0xffffffffu, comp, srcLane);
            float4 w = *(const float4*)(Wb + i * SIC + j);
            acc.x += xi * w.x; acc.y += xi * w.y;
            acc.z += xi * w.z; acc.w += xi * w.w;
        }
        acc.x *= nrm; acc.y *= nrm; acc.z *= nrm; acc.w *= nrm;
        atomicAdd(((float4*)(agg + (long)d * HH)) + lane, acc);   // sm_90+ vector RED
    }
}

// ---------------- C[8192,HB] = A[8192,128] @ B[128,HB]  (+addM +bias, relu) -------
// tile 128x64, 256 threads, 8x4 per thread
__global__ void __launch_bounds__(256) k_gemm(
    const float* __restrict__ A, const float* __restrict__ B,
    float* __restrict__ C, int HB,
    const float* __restrict__ addM, const float* __restrict__ bias, int relu)
{
    __shared__ float As[16][128];
    __shared__ float Bs[16][64];
    int bm = blockIdx.x * 128;
    int bn = blockIdx.y * 64;
    int tid = threadIdx.x;
    int tx = tid & 15, ty = tid >> 4;

    float acc[8][4];
    #pragma unroll
    for (int r = 0; r < 8; r++)
        #pragma unroll
        for (int c = 0; c < 4; c++) acc[r][c] = 0.f;

    for (int k0 = 0; k0 < HH; k0 += 16) {
        #pragma unroll
        for (int q = 0; q < 2; q++) {
            int fid = tid * 2 + q;          // 0..511, 4 float4 per A row
            int m = fid >> 2;
            int kk = (fid & 3) << 2;
            float4 v = *(const float4*)&A[(long)(bm + m) * HH + k0 + kk];
            As[kk + 0][m] = v.x; As[kk + 1][m] = v.y;
            As[kk + 2][m] = v.z; As[kk + 3][m] = v.w;
        }
        {
            int kk = tid >> 4;
            int nn = (tid & 15) << 2;
            *(float4*)&Bs[kk][nn] = *(const float4*)&B[(long)(k0 + kk) * HB + bn + nn];
        }
        __syncthreads();
        #pragma unroll
        for (int k = 0; k < 16; k++) {
            float4 a0 = *(float4*)&As[k][ty * 8];
            float4 a1 = *(float4*)&As[k][ty * 8 + 4];
            float4 bv = *(float4*)&Bs[k][tx * 4];
            float a[8] = {a0.x, a0.y, a0.z, a0.w, a1.x, a1.y, a1.z, a1.w};
            float bb[4] = {bv.x, bv.y, bv.z, bv.w};
            #pragma unroll
            for (int r = 0; r < 8; r++)
                #pragma unroll
                for (int c = 0; c < 4; c++)
                    acc[r][c] += a[r] * bb[c];
        }
        __syncthreads();
    }

    #pragma unroll
    for (int r = 0; r < 8; r++) {
        long row = bm + ty * 8 + r;
        int colb = bn + tx * 4;
        float4 v = make_float4(acc[r][0], acc[r][1], acc[r][2], acc[r][3]);
        if (bias) {
            v.x += bias[colb]; v.y += bias[colb + 1];
            v.z += bias[colb + 2]; v.w += bias[colb + 3];
        }
        if (addM) {
            float4 m = *(const float4*)&addM[row * HB + colb];
            v.x += m.x; v.y += m.y; v.z += m.z; v.w += m.w;
        }
        if (relu) {
            v.x = fmaxf(v.x, 0.f); v.y = fmaxf(v.y, 0.f);
            v.z = fmaxf(v.z, 0.f); v.w = fmaxf(v.w, 0.f);
        }
        *(float4*)&C[row * HB + colb] = v;
    }
}

// ---------------- S[128,128] += A^T[128,8192] @ B[8192,128], split-K -----------
// grid 128 blocks, each owns 64 K-rows; atomicAdd partials into S (pre-zeroed)
__global__ void __launch_bounds__(256) k_gemm_red(
    const float* __restrict__ A, const float* __restrict__ B, float* __restrict__ S)
{
    __shared__ float As[16][128];
    __shared__ float Bs[16][128];
    int k0base = blockIdx.x * 64;
    int tid = threadIdx.x, tx = tid & 15, ty = tid >> 4;

    float acc[8][8];
    #pragma unroll
    for (int r = 0; r < 8; r++)
        #pragma unroll
        for (int c = 0; c < 8; c++) acc[r][c] = 0.f;

    for (int k0 = k0base; k0 < k0base + 64; k0 += 16) {
        #pragma unroll
        for (int q = 0; q < 2; q++) {
            int fid = tid * 2 + q;          // 0..511, 32 float4 per row
            int kk = fid >> 5;
            int mm = (fid & 31) << 2;
            *(float4*)&As[kk][mm] = *(const float4*)&A[(long)(k0 + kk) * HH + mm];
            *(float4*)&Bs[kk][mm] = *(const float4*)&B[(long)(k0 + kk) * HH + mm];
        }
        __syncthreads();
        #pragma unroll
        for (int k = 0; k < 16; k++) {
            float4 a0 = *(float4*)&As[k][ty * 8];
            float4 a1 = *(float4*)&As[k][ty * 8 + 4];
            float4 b0 = *(float4*)&Bs[k][tx * 8];
            float4 b1 = *(float4*)&Bs[k][tx * 8 + 4];
            float a[8] = {a0.x, a0.y, a0.z, a0.w, a1.x, a1.y, a1.z, a1.w};
            float b[8] = {b0.x, b0.y, b0.z, b0.w, b1.x, b1.y, b1.z, b1.w};
            #pragma unroll
            for (int r = 0; r < 8; r++)
                #pragma unroll
                for (int c = 0; c < 8; c++)
                    acc[r][c] += a[r] * b[c];
        }
        __syncthreads();
    }

    #pragma unroll
    for (int r = 0; r < 8; r++)
        #pragma unroll
        for (int c = 0; c < 8; c++)
            atomicAdd(&S[(ty * 8 + r) * HH + tx * 8 + c], acc[r][c]);
}

// ---------------- launch ----------------
extern "C" void kernel_launch(void* const* d_in, const int* in_sizes, int n_in,
                              void* d_out, int out_size) {
    (void)in_sizes; (void)n_in; (void)out_size;
    const int*   node_ids = (const int*)  d_in[0];
    const int*   src      = (const int*)  d_in[1];
    const int*   dst      = (const int*)  d_in[2];
    const int*   et       = (const int*)  d_in[3];
    const float* norm     = (const float*)d_in[4];
    const float* eps      = (const float*)d_in[5];
    const float* emb      = (const float*)d_in[6];
    const float* W0       = (const float*)d_in[7];
    const float* loop0    = (const float*)d_in[8];
    const float* b0       = (const float*)d_in[9];
    const float* W1       = (const float*)d_in[10];
    const float* loop1    = (const float*)d_in[11];
    const float* b1       = (const float*)d_in[12];
    const float* Wz       = (const float*)d_in[13];
    const float* bz       = (const float*)d_in[14];
    const float* Wi       = (const float*)d_in[15];
    const float* bi       = (const float*)d_in[16];
    const float* hbi      = (const float*)d_in[17];
    const float* Wo       = (const float*)d_in[18];
    const float* bo       = (const float*)d_in[19];
    const float* hbo      = (const float*)d_in[20];
    float* out = (float*)d_out;

    float *p_x0, *p_h1, *p_h2, *p_agg, *p_zml, *p_z, *p_M, *p_h3, *p_S;
    cudaGetSymbolAddress((void**)&p_x0,  g_x0);
    cudaGetSymbolAddress((void**)&p_h1,  g_h1);
    cudaGetSymbolAddress((void**)&p_h2,  g_h2);
    cudaGetSymbolAddress((void**)&p_agg, g_agg);
    cudaGetSymbolAddress((void**)&p_zml, g_zml);
    cudaGetSymbolAddress((void**)&p_z,   g_z);
    cudaGetSymbolAddress((void**)&p_M,   g_M);
    cudaGetSymbolAddress((void**)&p_h3,  g_h3);
    cudaGetSymbolAddress((void**)&p_S,   g_S);

    const int AGG4 = NN * HH / 4;
    const int S4   = HH * HH / 4;

    // input embed + edge counting sort by relation
    k_zero_cnt<<<1, 128>>>();
    k_gather<<<NN * 32 / 256, 256>>>(emb, node_ids);
    k_hist<<<EE / 256, 256>>>(et);
    k_scan<<<1, 32>>>();
    k_permute<<<EE / 256, 256>>>(et);

    // RGCN layer 0: h1 = relu(agg + b0 + x0 @ loop0)
    k_zero<<<(AGG4 + 255) / 256, 256>>>(p_agg, AGG4);
    k_edge<<<dim3(24, NRELC), 256>>>(p_x0, W0, src, dst, norm, p_agg);
    k_gemm<<<dim3(64, 2), 256>>>(p_x0, loop0, p_h1, HH, p_agg, b0, 1);

    // RGCN layer 1: h2 = agg + b1 + h1 @ loop1
    k_zero<<<(AGG4 + 255) / 256, 256>>>(p_agg, AGG4);
    k_edge<<<dim3(24, NRELC), 256>>>(p_h1, W1, src, dst, norm, p_agg);
    k_gemm<<<dim3(64, 2), 256>>>(p_h1, loop1, p_h2, HH, p_agg, b1, 0);

    // VAE head: zml = h2 @ Wz + bz ; z = mean + exp(log_std)*eps
    k_gemm<<<dim3(64, 4), 256>>>(p_h2, Wz, p_zml, 2 * HH, nullptr, bz, 0);
    k_z<<<NN * HH / 256, 256>>>(eps);

    // decode 1: h = z @ (z^T @ (z@Wi + bi + x0)) + hbi     [R@M == z(z^T M)]
    k_gemm<<<dim3(64, 2), 256>>>(p_z, Wi, p_M, HH, p_x0, bi, 0);
    k_zero<<<(S4 + 255) / 256, 256>>>(p_S, S4);
    k_gemm_red<<<128, 256>>>(p_z, p_M, p_S);
    k_gemm<<<dim3(64, 2), 256>>>(p_z, p_S, p_h3, HH, nullptr, hbi, 0);

    // decode 2: out = h @ (h^T @ (h@Wo + bo + x0)) + hbo
    k_gemm<<<dim3(64, 2), 256>>>(p_h3, Wo, p_M, HH, p_x0, bo, 0);
    k_zero<<<(S4 + 255) / 256, 256>>>(p_S, S4);
    k_gemm_red<<<128, 256>>>(p_h3, p_M, p_S);
    k_gemm<<<dim3(64, 2), 256>>>(p_h3, p_S, out, HH, nullptr, hbo, 0);
}

// round 6
// speedup vs baseline: 1.3480x; 1.3480x over previous
#include <cuda_runtime.h>

#define NN   8192
#define HH   128
#define EE   131072
#define NRELC 90
#define NBC  8
#define SIC  16

// ---------------- device scratch (no allocations allowed) ----------------
__device__ float g_x0[NN*HH];
__device__ float g_h1[NN*HH];
__device__ float g_h2[NN*HH];
__device__ float g_agg[NN*HH];
__device__ float g_zml[NN*2*HH];
__device__ float g_z[NN*HH];
__device__ float g_M[NN*HH];
__device__ float g_h3[NN*HH];
__device__ float g_S[HH*HH];
__device__ int   g_srcS[EE];
__device__ int   g_dstS[EE];
__device__ float g_normS[EE];
__device__ int   g_cnt[NRELC];
__device__ int   g_off[NRELC+1];
__device__ int   g_cur[NRELC];

// ---------------- helpers ----------------
__device__ __forceinline__ unsigned f2tf(float f) {
    unsigned u;
    asm("cvt.rna.tf32.f32 %0, %1;" : "=r"(u) : "f"(f));
    return u;
}

__device__ __forceinline__ void mma_tf32(
    float& c0, float& c1, float& c2, float& c3,
    unsigned a0, unsigned a1, unsigned a2, unsigned a3,
    unsigned b0, unsigned b1)
{
    asm("mma.sync.aligned.m16n8k8.row.col.f32.tf32.tf32.f32 "
        "{%0,%1,%2,%3},{%4,%5,%6,%7},{%8,%9},{%0,%1,%2,%3};"
        : "+f"(c0), "+f"(c1), "+f"(c2), "+f"(c3)
        : "r"(a0), "r"(a1), "r"(a2), "r"(a3), "r"(b0), "r"(b1));
}

// ---------------- trivial kernels ----------------
__global__ void k_zero(float* __restrict__ p, int n4) {
    int i = blockIdx.x * blockDim.x + threadIdx.x;
    if (i < n4) ((float4*)p)[i] = make_float4(0.f, 0.f, 0.f, 0.f);
}

__global__ void k_zero_cnt() {
    int i = threadIdx.x;
    if (i < NRELC) g_cnt[i] = 0;
}

__global__ void k_gather(const float* __restrict__ emb, const int* __restrict__ ids) {
    int i = blockIdx.x * blockDim.x + threadIdx.x;   // over NN*32 float4
    int row = i >> 5, c = i & 31;
    int nid = ids[row];
    ((float4*)g_x0)[i] = ((const float4*)emb)[nid * 32 + c];
}

__global__ void k_hist(const int* __restrict__ et) {
    int i = blockIdx.x * blockDim.x + threadIdx.x;
    if (i < EE) atomicAdd(&g_cnt[et[i]], 1);
}

// parallel scan over 90 relation counts (128-thread Hillis-Steele)
__global__ void k_scan() {
    __shared__ int s[128];
    int t = threadIdx.x;
    int v = (t < NRELC) ? g_cnt[t] : 0;
    s[t] = v;
    __syncthreads();
    #pragma unroll
    for (int off = 1; off < 128; off <<= 1) {
        int x = (t >= off) ? s[t - off] : 0;
        __syncthreads();
        s[t] += x;
        __syncthreads();
    }
    if (t < NRELC) {
        int excl = s[t] - v;
        g_off[t] = excl;
        g_cur[t] = excl;
    }
    if (t == NRELC - 1) g_off[NRELC] = s[t];
}

// counting-sort scatter: also gathers src/dst/norm into sorted order so the
// edge kernel reads them coalesced.
__global__ void k_permute(const int* __restrict__ et,
                          const int* __restrict__ src, const int* __restrict__ dst,
                          const float* __restrict__ norm) {
    int i = blockIdx.x * blockDim.x + threadIdx.x;
    if (i < EE) {
        int p = atomicAdd(&g_cur[et[i]], 1);
        g_srcS[p]  = src[i];
        g_dstS[p]  = dst[i];
        g_normS[p] = norm[i];
    }
}

__global__ void k_z(const float* __restrict__ eps) {
    int i = blockIdx.x * blockDim.x + threadIdx.x;   // over NN*HH
    int row = i >> 7, col = i & 127;
    float m  = g_zml[row * 256 + col];
    float ls = g_zml[row * 256 + 128 + col];
    g_z[i] = m + expf(ls) * eps[i];
}

// ---------------- RGCN edge message kernel (sorted by relation) ----------------
// grid: (CHUNKS, NREL), block 256 = 8 warps, 1 warp per edge.
// Each lane computes 4 consecutive output elements (one float4 atomicAdd).
__global__ void __launch_bounds__(256) k_edge(
    const float* __restrict__ x, const float* __restrict__ W,
    float* __restrict__ agg)
{
    __shared__ float Ws[NBC * SIC * SIC];   // 2048 floats = 8 KB
    int rel = blockIdx.y;
    int start = g_off[rel], end = g_off[rel + 1];
    if (start == end) return;

    for (int i = threadIdx.x; i < NBC * SIC * SIC; i += 256)
        Ws[i] = W[rel * NBC * SIC * SIC + i];
    __syncthreads();

    int warp = threadIdx.x >> 5, lane = threadIdx.x & 31;
    int b = lane >> 2;                    // block-diag block 0..7
    int j = (lane & 3) << 2;              // output col base within block
    const float* Wb = Ws + b * (SIC * SIC);

    for (int idx = start + blockIdx.x * 8 + warp; idx < end; idx += gridDim.x * 8) {
        int s = g_srcS[idx], d = g_dstS[idx];
        float nrm = g_normS[idx];
        float4 xv = ((const float4*)(x + (long)s * HH))[lane];  // lane holds x[4*lane..]

        float4 acc = make_float4(0.f, 0.f, 0.f, 0.f);
        #pragma unroll
        for (int i = 0; i < SIC; i++) {
            // value x[b*16 + i] lives in lane (b*4 + i/4), component i%4
            int srcLane = (lane & 28) + (i >> 2);
            float comp;
            switch (i & 3) {
                case 0: comp = xv.x; break;
                case 1: comp = xv.y; break;
                case 2: comp = xv.z; break;
                default: comp = xv.w; break;
            }
            float xi = __shfl_sync(0xffffffffu, comp, srcLane);
            float4 w = *(const float4*)(Wb + i * SIC + j);
            acc.x += xi * w.x; acc.y += xi * w.y;
            acc.z += xi * w.z; acc.w += xi * w.w;
        }
        acc.x *= nrm; acc.y *= nrm; acc.z *= nrm; acc.w *= nrm;
        atomicAdd(((float4*)(agg + (long)d * HH)) + lane, acc);   // sm_90+ vector RED
    }
}

// ---------------- C[8192,HB] = A[8192,128] @ B[128,HB] via tf32 mma.sync ----------
// tile 128x64 per block, 8 warps in 4(m)x2(n): warp tile 32x32.
// K=128 streamed in 4 chunks of 32, 4 k8-steps per chunk.
__global__ void __launch_bounds__(256) k_gemm_mma(
    const float* __restrict__ A, const float* __restrict__ B,
    float* __restrict__ C, int HB,
    const float* __restrict__ addM, const float* __restrict__ bias, int relu)
{
    __shared__ unsigned As[128][36];   // [m][k] tf32, pad 36 -> bank (4m+k)%32
    __shared__ unsigned Bs[32][72];    // [k][n] tf32, pad 72 -> bank (8k+n)%32
    int bm = blockIdx.x * 128;
    int bn = blockIdx.y * 64;
    int tid = threadIdx.x, w = tid >> 5, lane = tid & 31;
    int g = lane >> 2, tg = lane & 3;
    int wm = (w >> 1) * 32, wn = (w & 1) * 32;

    float acc[2][4][4];
    #pragma unroll
    for (int mt = 0; mt < 2; mt++)
        #pragma unroll
        for (int nt = 0; nt < 4; nt++)
            #pragma unroll
            for (int q = 0; q < 4; q++) acc[mt][nt][q] = 0.f;

    for (int kc = 0; kc < 4; kc++) {
        int k0 = kc * 32;
        // load A chunk 128x32 (1024 float4 / 256 thr = 4 each)
        #pragma unroll
        for (int it = 0; it < 4; it++) {
            int fid = tid + it * 256;
            int row = fid >> 3;
            int c4 = (fid & 7) << 2;
            float4 v = *(const float4*)&A[(long)(bm + row) * HH + k0 + c4];
            As[row][c4 + 0] = f2tf(v.x); As[row][c4 + 1] = f2tf(v.y);
            As[row][c4 + 2] = f2tf(v.z); As[row][c4 + 3] = f2tf(v.w);
        }
        // load B chunk 32x64 (512 float4 / 256 thr = 2 each)
        #pragma unroll
        for (int it = 0; it < 2; it++) {
            int fid = tid + it * 256;
            int row = fid >> 4;
            int c4 = (fid & 15) << 2;
            float4 v = *(const float4*)&B[(long)(k0 + row) * HB + bn + c4];
            Bs[row][c4 + 0] = f2tf(v.x); Bs[row][c4 + 1] = f2tf(v.y);
            Bs[row][c4 + 2] = f2tf(v.z); Bs[row][c4 + 3] = f2tf(v.w);
        }
        __syncthreads();

        #pragma unroll
        for (int ks = 0; ks < 4; ks++) {
            int kk = ks * 8;
            unsigned b0[4], b1[4];
            #pragma unroll
            for (int nt = 0; nt < 4; nt++) {
                b0[nt] = Bs[kk + tg][wn + nt * 8 + g];
                b1[nt] = Bs[kk + tg + 4][wn + nt * 8 + g];
            }
            #pragma unroll
            for (int mt = 0; mt < 2; mt++) {
                int rb = wm + mt * 16;
                unsigned a0 = As[rb + g][kk + tg];
                unsigned a1 = As[rb + g + 8][kk + tg];
                unsigned a2 = As[rb + g][kk + tg + 4];
                unsigned a3 = As[rb + g + 8][kk + tg + 4];
                #pragma unroll
                for (int nt = 0; nt < 4; nt++)
                    mma_tf32(acc[mt][nt][0], acc[mt][nt][1], acc[mt][nt][2], acc[mt][nt][3],
                             a0, a1, a2, a3, b0[nt], b1[nt]);
            }
        }
        __syncthreads();
    }

    // epilogue: c0/c1 at (row0, col..col+1), c2/c3 at (row0+8, col..col+1)
    #pragma unroll
    for (int mt = 0; mt < 2; mt++) {
        #pragma unroll
        for (int nt = 0; nt < 4; nt++) {
            int col = bn + wn + nt * 8 + 2 * tg;
            float bx = 0.f, by = 0.f;
            if (bias) { bx = bias[col]; by = bias[col + 1]; }
            #pragma unroll
            for (int h = 0; h < 2; h++) {
                long row = bm + wm + mt * 16 + g + h * 8;
                float vx = acc[mt][nt][2 * h] + bx;
                float vy = acc[mt][nt][2 * h + 1] + by;
                if (addM) {
                    float2 m = *(const float2*)&addM[row * HB + col];
                    vx += m.x; vy += m.y;
                }
                if (relu) { vx = fmaxf(vx, 0.f); vy = fmaxf(vy, 0.f); }
                *(float2*)&C[row * HB + col] = make_float2(vx, vy);
            }
        }
    }
}

// ---------------- S[128,128] += A^T[128,8192] @ B[8192,128] via tf32 mma, split-K ----
// grid 128 blocks, each owns 64 K-rows. Block computes the full 128x128 tile,
// warps arranged 2(m)x4(n): warp tile 64x32. atomicAdd partials into S (pre-zeroed).
__global__ void __launch_bounds__(256) k_gemm_red_mma(
    const float* __restrict__ A, const float* __restrict__ B, float* __restrict__ S)
{
    __shared__ unsigned Ak[32][136];   // [k][m] tf32, pad 136 -> bank (8k+m)%32
    __shared__ unsigned Bs[32][136];   // [k][n]
    int k0base = blockIdx.x * 64;
    int tid = threadIdx.x, w = tid >> 5, lane = tid & 31;
    int g = lane >> 2, tg = lane & 3;
    int wm = (w >> 2) * 64, wn = (w & 3) * 32;

    float acc[4][4][4];
    #pragma unroll
    for (int mt = 0; mt < 4; mt++)
        #pragma unroll
        for (int nt = 0; nt < 4; nt++)
            #pragma unroll
            for (int q = 0; q < 4; q++) acc[mt][nt][q] = 0.f;

    for (int kc = 0; kc < 2; kc++) {
        int k0 = k0base + kc * 32;
        // load A chunk 32x128 and B chunk 32x128 (each 1024 float4 / 256 thr = 4)
        #pragma unroll
        for (int it = 0; it < 4; it++) {
            int fid = tid + it * 256;
            int row = fid >> 5;
            int c4 = (fid & 31) << 2;
            float4 va = *(const float4*)&A[(long)(k0 + row) * HH + c4];
            Ak[row][c4 + 0] = f2tf(va.x); Ak[row][c4 + 1] = f2tf(va.y);
            Ak[row][c4 + 2] = f2tf(va.z); Ak[row][c4 + 3] = f2tf(va.w);
            float4 vb = *(const float4*)&B[(long)(k0 + row) * HH + c4];
            Bs[row][c4 + 0] = f2tf(vb.x); Bs[row][c4 + 1] = f2tf(vb.y);
            Bs[row][c4 + 2] = f2tf(vb.z); Bs[row][c4 + 3] = f2tf(vb.w);
        }
        __syncthreads();

        #pragma unroll
        for (int ks = 0; ks < 4; ks++) {
            int kk = ks * 8;
            unsigned b0[4], b1[4];
            #pragma unroll
            for (int nt = 0; nt < 4; nt++) {
                b0[nt] = Bs[kk + tg][wn + nt * 8 + g];
                b1[nt] = Bs[kk + tg + 4][wn + nt * 8 + g];
            }
            #pragma unroll
            for (int mt = 0; mt < 4; mt++) {
                int mb = wm + mt * 16;
                // A-fragment of A^T: a(row=m,col=k) = A[k][m]
                unsigned a0 = Ak[kk + tg][mb + g];
                unsigned a1 = Ak[kk + tg][mb + g + 8];
                unsigned a2 = Ak[kk + tg + 4][mb + g];
                unsigned a3 = Ak[kk + tg + 4][mb + g + 8];
                #pragma unroll
                for (int nt = 0; nt < 4; nt++)
                    mma_tf32(acc[mt][nt][0], acc[mt][nt][1], acc[mt][nt][2], acc[mt][nt][3],
                             a0, a1, a2, a3, b0[nt], b1[nt]);
            }
        }
        __syncthreads();
    }

    #pragma unroll
    for (int mt = 0; mt < 4; mt++) {
        #pragma unroll
        for (int nt = 0; nt < 4; nt++) {
            int col = wn + nt * 8 + 2 * tg;
            #pragma unroll
            for (int h = 0; h < 2; h++) {
                int row = wm + mt * 16 + g + h * 8;
                atomicAdd(&S[row * HH + col],     acc[mt][nt][2 * h]);
                atomicAdd(&S[row * HH + col + 1], acc[mt][nt][2 * h + 1]);
            }
        }
    }
}

// ---------------- launch ----------------
extern "C" void kernel_launch(void* const* d_in, const int* in_sizes, int n_in,
                              void* d_out, int out_size) {
    (void)in_sizes; (void)n_in; (void)out_size;
    const int*   node_ids = (const int*)  d_in[0];
    const int*   src      = (const int*)  d_in[1];
    const int*   dst      = (const int*)  d_in[2];
    const int*   et       = (const int*)  d_in[3];
    const float* norm     = (const float*)d_in[4];
    const float* eps      = (const float*)d_in[5];
    const float* emb      = (const float*)d_in[6];
    const float* W0       = (const float*)d_in[7];
    const float* loop0    = (const float*)d_in[8];
    const float* b0       = (const float*)d_in[9];
    const float* W1       = (const float*)d_in[10];
    const float* loop1    = (const float*)d_in[11];
    const float* b1       = (const float*)d_in[12];
    const float* Wz       = (const float*)d_in[13];
    const float* bz       = (const float*)d_in[14];
    const float* Wi       = (const float*)d_in[15];
    const float* bi       = (const float*)d_in[16];
    const float* hbi      = (const float*)d_in[17];
    const float* Wo       = (const float*)d_in[18];
    const float* bo       = (const float*)d_in[19];
    const float* hbo      = (const float*)d_in[20];
    float* out = (float*)d_out;

    float *p_x0, *p_h1, *p_h2, *p_agg, *p_zml, *p_z, *p_M, *p_h3, *p_S;
    cudaGetSymbolAddress((void**)&p_x0,  g_x0);
    cudaGetSymbolAddress((void**)&p_h1,  g_h1);
    cudaGetSymbolAddress((void**)&p_h2,  g_h2);
    cudaGetSymbolAddress((void**)&p_agg, g_agg);
    cudaGetSymbolAddress((void**)&p_zml, g_zml);
    cudaGetSymbolAddress((void**)&p_z,   g_z);
    cudaGetSymbolAddress((void**)&p_M,   g_M);
    cudaGetSymbolAddress((void**)&p_h3,  g_h3);
    cudaGetSymbolAddress((void**)&p_S,   g_S);

    const int AGG4 = NN * HH / 4;
    const int S4   = HH * HH / 4;

    // input embed + edge counting sort by relation
    k_zero_cnt<<<1, 128>>>();
    k_gather<<<NN * 32 / 256, 256>>>(emb, node_ids);
    k_hist<<<EE / 256, 256>>>(et);
    k_scan<<<1, 128>>>();
    k_permute<<<EE / 256, 256>>>(et, src, dst, norm);

    // RGCN layer 0: h1 = relu(agg + b0 + x0 @ loop0)
    k_zero<<<(AGG4 + 255) / 256, 256>>>(p_agg, AGG4);
    k_edge<<<dim3(24, NRELC), 256>>>(p_x0, W0, p_agg);
    k_gemm_mma<<<dim3(64, 2), 256>>>(p_x0, loop0, p_h1, HH, p_agg, b0, 1);

    // RGCN layer 1: h2 = agg + b1 + h1 @ loop1
    k_zero<<<(AGG4 + 255) / 256, 256>>>(p_agg, AGG4);
    k_edge<<<dim3(24, NRELC), 256>>>(p_h1, W1, p_agg);
    k_gemm_mma<<<dim3(64, 2), 256>>>(p_h1, loop1, p_h2, HH, p_agg, b1, 0);

    // VAE head: zml = h2 @ Wz + bz ; z = mean + exp(log_std)*eps
    k_gemm_mma<<<dim3(64, 4), 256>>>(p_h2, Wz, p_zml, 2 * HH, nullptr, bz, 0);
    k_z<<<NN * HH / 256, 256>>>(eps);

    // decode 1: h = z @ (z^T @ (z@Wi + bi + x0)) + hbi     [R@M == z(z^T M)]
    k_gemm_mma<<<dim3(64, 2), 256>>>(p_z, Wi, p_M, HH, p_x0, bi, 0);
    k_zero<<<(S4 + 255) / 256, 256>>>(p_S, S4);
    k_gemm_red_mma<<<128, 256>>>(p_z, p_M, p_S);
    k_gemm_mma<<<dim3(64, 2), 256>>>(p_z, p_S, p_h3, HH, nullptr, hbi, 0);

    // decode 2: out = h @ (h^T @ (h@Wo + bo + x0)) + hbo
    k_gemm_mma<<<dim3(64, 2), 256>>>(p_h3, Wo, p_M, HH, p_x0, bo, 0);
    k_zero<<<(S4 + 255) / 256, 256>>>(p_S, S4);
    k_gemm_red_mma<<<128, 256>>>(p_h3, p_M, p_S);
    k_gemm_mma<<<dim3(64, 2), 256>>>(p_h3, p_S, out, HH, nullptr, hbo, 0);
}

// round 10
// speedup vs baseline: 1.6191x; 1.2011x over previous
#include <cuda_runtime.h>

#define NN   8192
#define HH   128
#define EE   131072
#define NRELC 90
#define NBC  8
#define SIC  16

// ---------------- device scratch (no allocations allowed) ----------------
__device__ float g_x0[NN*HH];
__device__ float g_h1[NN*HH];
__device__ float g_h2[NN*HH];
__device__ float g_agg[NN*HH];
__device__ float g_z[NN*HH];
__device__ float g_M[NN*HH];
__device__ float g_h3[NN*HH];
__device__ float g_S[HH*HH];
__device__ int   g_srcS[EE];
__device__ int   g_dstS[EE];
__device__ float g_normS[EE];
__device__ int   g_cnt[NRELC];
__device__ int   g_off[NRELC+1];
__device__ int   g_cur[NRELC];

// ---------------- helpers ----------------
__device__ __forceinline__ unsigned f2tf(float f) {
    unsigned u;
    asm("cvt.rna.tf32.f32 %0, %1;" : "=r"(u) : "f"(f));
    return u;
}

__device__ __forceinline__ void mma_tf32(
    float& c0, float& c1, float& c2, float& c3,
    unsigned a0, unsigned a1, unsigned a2, unsigned a3,
    unsigned b0, unsigned b1)
{
    asm("mma.sync.aligned.m16n8k8.row.col.f32.tf32.tf32.f32 "
        "{%0,%1,%2,%3},{%4,%5,%6,%7},{%8,%9},{%0,%1,%2,%3};"
        : "+f"(c0), "+f"(c1), "+f"(c2), "+f"(c3)
        : "r"(a0), "r"(a1), "r"(a2), "r"(a3), "r"(b0), "r"(b1));
}

__device__ __forceinline__ unsigned long long pk2(float x, float y) {
    unsigned long long r;
    asm("mov.b64 %0, {%1, %2};" : "=l"(r) : "f"(x), "f"(y));
    return r;
}
__device__ __forceinline__ void fma2(unsigned long long &c, unsigned long long a, unsigned long long b) {
    asm("fma.rn.f32x2 %0, %1, %2, %0;" : "+l"(c) : "l"(a), "l"(b));
}
__device__ __forceinline__ void mul2(unsigned long long &c, unsigned long long a, unsigned long long b) {
    asm("mul.rn.f32x2 %0, %1, %2;" : "=l"(c) : "l"(a), "l"(b));
}
__device__ __forceinline__ float2 up2(unsigned long long v) {
    float2 f;
    asm("mov.b64 {%0, %1}, %2;" : "=f"(f.x), "=f"(f.y) : "l"(v));
    return f;
}

// ---------------- fused prologue: gather x0 + zero agg + zero cnt --------------
__global__ void k_gather(const float* __restrict__ emb, const int* __restrict__ ids) {
    int i = blockIdx.x * blockDim.x + threadIdx.x;   // over NN*32 float4
    int row = i >> 5, c = i & 31;
    int nid = ids[row];
    ((float4*)g_x0)[i]  = ((const float4*)emb)[nid * 32 + c];
    ((float4*)g_agg)[i] = make_float4(0.f, 0.f, 0.f, 0.f);
    if (blockIdx.x == 0 && threadIdx.x < NRELC) g_cnt[threadIdx.x] = 0;
}

__global__ void k_hist(const int* __restrict__ et) {
    int i = blockIdx.x * blockDim.x + threadIdx.x;
    if (i < EE) atomicAdd(&g_cnt[et[i]], 1);
}

// parallel scan over 90 relation counts (128-thread Hillis-Steele)
__global__ void k_scan() {
    __shared__ int s[128];
    int t = threadIdx.x;
    int v = (t < NRELC) ? g_cnt[t] : 0;
    s[t] = v;
    __syncthreads();
    #pragma unroll
    for (int off = 1; off < 128; off <<= 1) {
        int x = (t >= off) ? s[t - off] : 0;
        __syncthreads();
        s[t] += x;
        __syncthreads();
    }
    if (t < NRELC) {
        int excl = s[t] - v;
        g_off[t] = excl;
        g_cur[t] = excl;
    }
    if (t == NRELC - 1) g_off[NRELC] = s[t];
}

// counting-sort scatter: gathers src/dst/norm into sorted order (coalesced reads later)
__global__ void k_permute(const int* __restrict__ et,
                          const int* __restrict__ src, const int* __restrict__ dst,
                          const float* __restrict__ norm) {
    int i = blockIdx.x * blockDim.x + threadIdx.x;
    if (i < EE) {
        int p = atomicAdd(&g_cur[et[i]], 1);
        g_srcS[p]  = src[i];
        g_dstS[p]  = dst[i];
        g_normS[p] = norm[i];
    }
}

// ---------------- RGCN edge message kernel (sorted by relation) ----------------
// grid: (CHUNKS, NREL), block 256 = 8 warps, 1 warp per edge.
// W hoisted to registers (packed f32x2); per-lane direct x loads (no shuffles).
__global__ void __launch_bounds__(256) k_edge(
    const float* __restrict__ x, const float* __restrict__ W,
    float* __restrict__ agg)
{
    __shared__ float Ws[NBC * SIC * SIC];   // 8 KB
    int rel = blockIdx.y;
    int start = g_off[rel], end = g_off[rel + 1];
    if (start == end) return;

    for (int i = threadIdx.x; i < NBC * SIC * SIC; i += 256)
        Ws[i] = W[rel * NBC * SIC * SIC + i];
    __syncthreads();

    int warp = threadIdx.x >> 5, lane = threadIdx.x & 31;
    int b = lane >> 2;                    // block-diag block 0..7
    int j = (lane & 3) << 2;              // output col base within block

    unsigned long long wlo[SIC], whi[SIC];
    #pragma unroll
    for (int i = 0; i < SIC; i++) {
        float4 wv = *(const float4*)&Ws[b * 256 + i * SIC + j];
        wlo[i] = pk2(wv.x, wv.y);
        whi[i] = pk2(wv.z, wv.w);
    }

    for (int idx = start + blockIdx.x * 8 + warp; idx < end; idx += gridDim.x * 8) {
        int s = g_srcS[idx], d = g_dstS[idx];
        float nrm = g_normS[idx];
        const float4* xr = (const float4*)(x + (long)s * HH + b * SIC);
        float4 xa = xr[0], xb = xr[1], xc = xr[2], xd = xr[3];
        float xs[16] = {xa.x, xa.y, xa.z, xa.w, xb.x, xb.y, xb.z, xb.w,
                        xc.x, xc.y, xc.z, xc.w, xd.x, xd.y, xd.z, xd.w};

        unsigned long long alo = 0ull, ahi = 0ull;
        #pragma unroll
        for (int i = 0; i < SIC; i++) {
            unsigned long long xi2 = pk2(xs[i], xs[i]);
            fma2(alo, xi2, wlo[i]);
            fma2(ahi, xi2, whi[i]);
        }
        unsigned long long n2 = pk2(nrm, nrm);
        mul2(alo, alo, n2);
        mul2(ahi, ahi, n2);
        float2 lo = up2(alo), hi = up2(ahi);
        atomicAdd((float4*)(agg + (long)d * HH + b * SIC + j),
                  make_float4(lo.x, lo.y, hi.x, hi.y));
    }
}

// ---------------- C[8192,HB] = A[8192,128] @ B[128,HB] via tf32 mma ----------
// tile 128x64, 8 warps 4(m)x2(n), register-prefetch pipeline over 4 K-chunks.
// Optional: addM (+ clear it in place), bias, relu; extra grid.y row zeroes zbuf.
__global__ void __launch_bounds__(256) k_gemm_mma(
    const float* __restrict__ A, const float* __restrict__ B,
    float* __restrict__ C, int HB,
    float* __restrict__ addM, const float* __restrict__ bias,
    int relu, int clearAddM, float* __restrict__ zbuf)
{
    if (zbuf != nullptr && blockIdx.y == (int)gridDim.y - 1) {
        for (int i = blockIdx.x * 256 + threadIdx.x; i < HH * HH / 4; i += gridDim.x * 256)
            ((float4*)zbuf)[i] = make_float4(0.f, 0.f, 0.f, 0.f);
        return;
    }
    __shared__ unsigned As[128][36];
    __shared__ unsigned Bs[32][72];
    int bm = blockIdx.x * 128;
    int bn = blockIdx.y * 64;
    int tid = threadIdx.x, w = tid >> 5, lane = tid & 31;
    int g = lane >> 2, tg = lane & 3;
    int wm = (w >> 1) * 32, wn = (w & 1) * 32;

    int arow = tid >> 3, ac = (tid & 7) << 2;
    int brow = tid >> 4, bc = (tid & 15) << 2;

    float4 ra[4], rb[2];
    #pragma unroll
    for (int it = 0; it < 4; it++)
        ra[it] = *(const float4*)&A[(long)(bm + arow + it * 32) * HH + ac];
    #pragma unroll
    for (int it = 0; it < 2; it++)
        rb[it] = *(const float4*)&B[(long)(brow + it * 16) * HB + bn + bc];

    float acc[2][4][4];
    #pragma unroll
    for (int mt = 0; mt < 2; mt++)
        #pragma unroll
        for (int nt = 0; nt < 4; nt++)
            #pragma unroll
            for (int q = 0; q < 4; q++) acc[mt][nt][q] = 0.f;

    for (int kc = 0; kc < 4; kc++) {
        #pragma unroll
        for (int it = 0; it < 4; it++) {
            int r = arow + it * 32;
            As[r][ac + 0] = f2tf(ra[it].x); As[r][ac + 1] = f2tf(ra[it].y);
            As[r][ac + 2] = f2tf(ra[it].z); As[r][ac + 3] = f2tf(ra[it].w);
        }
        #pragma unroll
        for (int it = 0; it < 2; it++) {
            int r = brow + it * 16;
            Bs[r][bc + 0] = f2tf(rb[it].x); Bs[r][bc + 1] = f2tf(rb[it].y);
            Bs[r][bc + 2] = f2tf(rb[it].z); Bs[r][bc + 3] = f2tf(rb[it].w);
        }
        __syncthreads();
        if (kc < 3) {
            int k0 = (kc + 1) * 32;
            #pragma unroll
            for (int it = 0; it < 4; it++)
                ra[it] = *(const float4*)&A[(long)(bm + arow + it * 32) * HH + k0 + ac];
            #pragma unroll
            for (int it = 0; it < 2; it++)
                rb[it] = *(const float4*)&B[(long)(k0 + brow + it * 16) * HB + bn + bc];
        }
        #pragma unroll
        for (int ks = 0; ks < 4; ks++) {
            int kk = ks * 8;
            unsigned b0[4], b1[4];
            #pragma unroll
            for (int nt = 0; nt < 4; nt++) {
                b0[nt] = Bs[kk + tg][wn + nt * 8 + g];
                b1[nt] = Bs[kk + tg + 4][wn + nt * 8 + g];
            }
            #pragma unroll
            for (int mt = 0; mt < 2; mt++) {
                int rbse = wm + mt * 16;
                unsigned a0 = As[rbse + g][kk + tg];
                unsigned a1 = As[rbse + g + 8][kk + tg];
                unsigned a2 = As[rbse + g][kk + tg + 4];
                unsigned a3 = As[rbse + g + 8][kk + tg + 4];
                #pragma unroll
                for (int nt = 0; nt < 4; nt++)
                    mma_tf32(acc[mt][nt][0], acc[mt][nt][1], acc[mt][nt][2], acc[mt][nt][3],
                             a0, a1, a2, a3, b0[nt], b1[nt]);
            }
        }
        __syncthreads();
    }

    #pragma unroll
    for (int mt = 0; mt < 2; mt++) {
        #pragma unroll
        for (int nt = 0; nt < 4; nt++) {
            int col = bn + wn + nt * 8 + 2 * tg;
            float bx = 0.f, by = 0.f;
            if (bias) { bx = bias[col]; by = bias[col + 1]; }
            #pragma unroll
            for (int h = 0; h < 2; h++) {
                long row = bm + wm + mt * 16 + g + h * 8;
                float vx = acc[mt][nt][2 * h] + bx;
                float vy = acc[mt][nt][2 * h + 1] + by;
                if (addM) {
                    float2 m = *(const float2*)&addM[row * HB + col];
                    vx += m.x; vy += m.y;
                    if (clearAddM)
                        *(float2*)&addM[row * HB + col] = make_float2(0.f, 0.f);
                }
                if (relu) { vx = fmaxf(vx, 0.f); vy = fmaxf(vy, 0.f); }
                *(float2*)&C[row * HB + col] = make_float2(vx, vy);
            }
        }
    }
}

// ---------------- fused VAE head: z = (h2@Wz+bz)[:,:128] + exp((h2@Wz+bz)[:,128:])*eps
// Each block computes BOTH the mean tile (cols bn..bn+63) and log-std tile
// (cols bn+128..), then writes z directly. No zml buffer, no k_z kernel.
__global__ void __launch_bounds__(256) k_gemm_z(
    const float* __restrict__ A, const float* __restrict__ B,   // B = Wz [128][256]
    const float* __restrict__ bz, const float* __restrict__ eps)
{
    __shared__ unsigned As[128][36];
    __shared__ unsigned Bs[2][32][72];
    int bm = blockIdx.x * 128;
    int bn = blockIdx.y * 64;
    int tid = threadIdx.x, w = tid >> 5, lane = tid & 31;
    int g = lane >> 2, tg = lane & 3;
    int wm = (w >> 1) * 32, wn = (w & 1) * 32;

    int arow = tid >> 3, ac = (tid & 7) << 2;
    int brow = tid >> 4, bc = (tid & 15) << 2;

    float4 ra[4], rb[2][2];
    #pragma unroll
    for (int it = 0; it < 4; it++)
        ra[it] = *(const float4*)&A[(long)(bm + arow + it * 32) * HH + ac];
    #pragma unroll
    for (int t = 0; t < 2; t++)
        #pragma unroll
        for (int it = 0; it < 2; it++)
            rb[t][it] = *(const float4*)&B[(long)(brow + it * 16) * 256 + bn + t * 128 + bc];

    float acc[2][2][4][4];
    #pragma unroll
    for (int t = 0; t < 2; t++)
        #pragma unroll
        for (int mt = 0; mt < 2; mt++)
            #pragma unroll
            for (int nt = 0; nt < 4; nt++)
                #pragma unroll
                for (int q = 0; q < 4; q++) acc[t][mt][nt][q] = 0.f;

    for (int kc = 0; kc < 4; kc++) {
        #pragma unroll
        for (int it = 0; it < 4; it++) {
            int r = arow + it * 32;
            As[r][ac + 0] = f2tf(ra[it].x); As[r][ac + 1] = f2tf(ra[it].y);
            As[r][ac + 2] = f2tf(ra[it].z); As[r][ac + 3] = f2tf(ra[it].w);
        }
        #pragma unroll
        for (int t = 0; t < 2; t++)
            #pragma unroll
            for (int it = 0; it < 2; it++) {
                int r = brow + it * 16;
                Bs[t][r][bc + 0] = f2tf(rb[t][it].x); Bs[t][r][bc + 1] = f2tf(rb[t][it].y);
                Bs[t][r][bc + 2] = f2tf(rb[t][it].z); Bs[t][r][bc + 3] = f2tf(rb[t][it].w);
            }
        __syncthreads();
        if (kc < 3) {
            int k0 = (kc + 1) * 32;
            #pragma unroll
            for (int it = 0; it < 4; it++)
                ra[it] = *(const float4*)&A[(long)(bm + arow + it * 32) * HH + k0 + ac];
            #pragma unroll
            for (int t = 0; t < 2; t++)
                #pragma unroll
                for (int it = 0; it < 2; it++)
                    rb[t][it] = *(const float4*)&B[(long)(k0 + brow + it * 16) * 256 + bn + t * 128 + bc];
        }
        #pragma unroll
        for (int ks = 0; ks < 4; ks++) {
            int kk = ks * 8;
            #pragma unroll
            for (int mt = 0; mt < 2; mt++) {
                int rbse = wm + mt * 16;
                unsigned a0 = As[rbse + g][kk + tg];
                unsigned a1 = As[rbse + g + 8][kk + tg];
                unsigned a2 = As[rbse + g][kk + tg + 4];
                unsigned a3 = As[rbse + g + 8][kk + tg + 4];
                #pragma unroll
                for (int t = 0; t < 2; t++)
                    #pragma unroll
                    for (int nt = 0; nt < 4; nt++) {
                        unsigned b0 = Bs[t][kk + tg][wn + nt * 8 + g];
                        unsigned b1 = Bs[t][kk + tg + 4][wn + nt * 8 + g];
                        mma_tf32(acc[t][mt][nt][0], acc[t][mt][nt][1],
                                 acc[t][mt][nt][2], acc[t][mt][nt][3],
                                 a0, a1, a2, a3, b0, b1);
                    }
            }
        }
        __syncthreads();
    }

    #pragma unroll
    for (int mt = 0; mt < 2; mt++) {
        #pragma unroll
        for (int nt = 0; nt < 4; nt++) {
            int zc = bn + wn + nt * 8 + 2 * tg;
            float bm0 = bz[zc],       bm1 = bz[zc + 1];
            float bl0 = bz[zc + 128], bl1 = bz[zc + 129];
            #pragma unroll
            for (int h = 0; h < 2; h++) {
                long row = bm + wm + mt * 16 + g + h * 8;
                float2 e = *(const float2*)&eps[row * HH + zc];
                float z0 = (acc[0][mt][nt][2 * h]     + bm0) + expf(acc[1][mt][nt][2 * h]     + bl0) * e.x;
                float z1 = (acc[0][mt][nt][2 * h + 1] + bm1) + expf(acc[1][mt][nt][2 * h + 1] + bl1) * e.y;
                *(float2*)&g_z[row * HH + zc] = make_float2(z0, z1);
            }
        }
    }
}

// ---------------- S[128,128] += A^T[128,8192] @ B[8192,128], split-K 64 ----------
// 64 blocks, each owns 128 K-rows; float2 atomics into pre-zeroed S.
__global__ void __launch_bounds__(256) k_gemm_red_mma(
    const float* __restrict__ A, const float* __restrict__ B, float* __restrict__ S)
{
    __shared__ unsigned Ak[32][136];   // [k][m]
    __shared__ unsigned Bs[32][136];   // [k][n]
    int k0base = blockIdx.x * 128;
    int tid = threadIdx.x, w = tid >> 5, lane = tid & 31;
    int g = lane >> 2, tg = lane & 3;
    int wm = (w >> 2) * 64, wn = (w & 3) * 32;

    int lrow = tid >> 5, lc = (tid & 31) << 2;

    float4 rA[4], rB[4];
    #pragma unroll
    for (int it = 0; it < 4; it++) {
        rA[it] = *(const float4*)&A[(long)(k0base + lrow + it * 8) * HH + lc];
        rB[it] = *(const float4*)&B[(long)(k0base + lrow + it * 8) * HH + lc];
    }

    float acc[4][4][4];
    #pragma unroll
    for (int mt = 0; mt < 4; mt++)
        #pragma unroll
        for (int nt = 0; nt < 4; nt++)
            #pragma unroll
            for (int q = 0; q < 4; q++) acc[mt][nt][q] = 0.f;

    for (int kc = 0; kc < 4; kc++) {
        #pragma unroll
        for (int it = 0; it < 4; it++) {
            int r = lrow + it * 8;
            Ak[r][lc + 0] = f2tf(rA[it].x); Ak[r][lc + 1] = f2tf(rA[it].y);
            Ak[r][lc + 2] = f2tf(rA[it].z); Ak[r][lc + 3] = f2tf(rA[it].w);
            Bs[r][lc + 0] = f2tf(rB[it].x); Bs[r][lc + 1] = f2tf(rB[it].y);
            Bs[r][lc + 2] = f2tf(rB[it].z); Bs[r][lc + 3] = f2tf(rB[it].w);
        }
        __syncthreads();
        if (kc < 3) {
            int k0 = k0base + (kc + 1) * 32;
            #pragma unroll
            for (int it = 0; it < 4; it++) {
                rA[it] = *(const float4*)&A[(long)(k0 + lrow + it * 8) * HH + lc];
                rB[it] = *(const float4*)&B[(long)(k0 + lrow + it * 8) * HH + lc];
            }
        }
        #pragma unroll
        for (int ks = 0; ks < 4; ks++) {
            int kk = ks * 8;
            unsigned b0[4], b1[4];
            #pragma unroll
            for (int nt = 0; nt < 4; nt++) {
                b0[nt] = Bs[kk + tg][wn + nt * 8 + g];
                b1[nt] = Bs[kk + tg + 4][wn + nt * 8 + g];
            }
            #pragma unroll
            for (int mt = 0; mt < 4; mt++) {
                int mb = wm + mt * 16;
                unsigned a0 = Ak[kk + tg][mb + g];
                unsigned a1 = Ak[kk + tg][mb + g + 8];
                unsigned a2 = Ak[kk + tg + 4][mb + g];
                unsigned a3 = Ak[kk + tg + 4][mb + g + 8];
                #pragma unroll
                for (int nt = 0; nt < 4; nt++)
                    mma_tf32(acc[mt][nt][0], acc[mt][nt][1], acc[mt][nt][2], acc[mt][nt][3],
                             a0, a1, a2, a3, b0[nt], b1[nt]);
            }
        }
        __syncthreads();
    }

    #pragma unroll
    for (int mt = 0; mt < 4; mt++)
        #pragma unroll
        for (int nt = 0; nt < 4; nt++) {
            int col = wn + nt * 8 + 2 * tg;
            #pragma unroll
            for (int h = 0; h < 2; h++) {
                int row = wm + mt * 16 + g + h * 8;
                atomicAdd((float2*)&S[row * HH + col],
                          make_float2(acc[mt][nt][2 * h], acc[mt][nt][2 * h + 1]));
            }
        }
}

// ---------------- launch ----------------
extern "C" void kernel_launch(void* const* d_in, const int* in_sizes, int n_in,
                              void* d_out, int out_size) {
    (void)in_sizes; (void)n_in; (void)out_size;
    const int*   node_ids = (const int*)  d_in[0];
    const int*   src      = (const int*)  d_in[1];
    const int*   dst      = (const int*)  d_in[2];
    const int*   et       = (const int*)  d_in[3];
    const float* norm     = (const float*)d_in[4];
    const float* eps      = (const float*)d_in[5];
    const float* emb      = (const float*)d_in[6];
    const float* W0       = (const float*)d_in[7];
    const float* loop0    = (const float*)d_in[8];
    const float* b0       = (const float*)d_in[9];
    const float* W1       = (const float*)d_in[10];
    const float* loop1    = (const float*)d_in[11];
    const float* b1       = (const float*)d_in[12];
    const float* Wz       = (const float*)d_in[13];
    const float* bz       = (const float*)d_in[14];
    const float* Wi       = (const float*)d_in[15];
    const float* bi       = (const float*)d_in[16];
    const float* hbi      = (const float*)d_in[17];
    const float* Wo       = (const float*)d_in[18];
    const float* bo       = (const float*)d_in[19];
    const float* hbo      = (const float*)d_in[20];
    float* out = (float*)d_out;

    float *p_x0, *p_h1, *p_h2, *p_agg, *p_z, *p_M, *p_h3, *p_S;
    cudaGetSymbolAddress((void**)&p_x0,  g_x0);
    cudaGetSymbolAddress((void**)&p_h1,  g_h1);
    cudaGetSymbolAddress((void**)&p_h2,  g_h2);
    cudaGetSymbolAddress((void**)&p_agg, g_agg);
    cudaGetSymbolAddress((void**)&p_z,   g_z);
    cudaGetSymbolAddress((void**)&p_M,   g_M);
    cudaGetSymbolAddress((void**)&p_h3,  g_h3);
    cudaGetSymbolAddress((void**)&p_S,   g_S);

    // prologue: gather x0 (+ zero agg, zero cnt), then counting sort by relation
    k_gather<<<NN * 32 / 256, 256>>>(emb, node_ids);
    k_hist<<<EE / 256, 256>>>(et);
    k_scan<<<1, 128>>>();
    k_permute<<<EE / 256, 256>>>(et, src, dst, norm);

    // RGCN layer 0: h1 = relu(agg + b0 + x0 @ loop0); epilogue clears agg for layer 1
    k_edge<<<dim3(12, NRELC), 256>>>(p_x0, W0, p_agg);
    k_gemm_mma<<<dim3(64, 2), 256>>>(p_x0, loop0, p_h1, HH, p_agg, b0, 1, 1, nullptr);

    // RGCN layer 1: h2 = agg + b1 + h1 @ loop1
    k_edge<<<dim3(12, NRELC), 256>>>(p_h1, W1, p_agg);
    k_gemm_mma<<<dim3(64, 2), 256>>>(p_h1, loop1, p_h2, HH, p_agg, b1, 0, 0, nullptr);

    // VAE head fused: z = mean + exp(log_std)*eps
    k_gemm_z<<<dim3(64, 2), 256>>>(p_h2, Wz, bz, eps);

    // decode 1: h3 = z @ (z^T @ (z@Wi + bi + x0)) + hbi   [R@M == z(z^T M)]
    k_gemm_mma<<<dim3(64, 3), 256>>>(p_z, Wi, p_M, HH, p_x0, bi, 0, 0, p_S); // extra row zeroes S
    k_gemm_red_mma<<<64, 256>>>(p_z, p_M, p_S);
    k_gemm_mma<<<dim3(64, 2), 256>>>(p_z, p_S, p_h3, HH, nullptr, hbi, 0, 0, nullptr);

    // decode 2: out = h3 @ (h3^T @ (h3@Wo + bo + x0)) + hbo
    k_gemm_mma<<<dim3(64, 3), 256>>>(p_h3, Wo, p_M, HH, p_x0, bo, 0, 0, p_S);
    k_gemm_red_mma<<<64, 256>>>(p_h3, p_M, p_S);
    k_gemm_mma<<<dim3(64, 2), 256>>>(p_h3, p_S, out, HH, nullptr, hbo, 0, 0, nullptr);
}

// round 12
// speedup vs baseline: 2.0265x; 1.2517x over previous
#include <cuda_runtime.h>

#define NN   8192
#define HH   128
#define EE   131072
#define NRELC 90
#define NBC  8
#define SIC  16

// ---------------- device scratch (no allocations allowed) ----------------
__device__ float g_x0[NN*HH];
__device__ float g_h1[NN*HH];
__device__ float g_h2[NN*HH];
__device__ float g_agg[NN*HH];
__device__ float g_z[NN*HH];
__device__ float g_M[NN*HH];
__device__ float g_h3[NN*HH];
__device__ float g_S[HH*HH];
__device__ int   g_srcS[EE];
__device__ int   g_dstS[EE];
__device__ float g_normS[EE];
__device__ int   g_cnt[NRELC];
__device__ int   g_off[NRELC+1];
__device__ int   g_cur[NRELC];

// ---------------- helpers ----------------
__device__ __forceinline__ unsigned f2tf(float f) {
    unsigned u;
    asm("cvt.rna.tf32.f32 %0, %1;" : "=r"(u) : "f"(f));
    return u;
}

__device__ __forceinline__ void mma_tf32(
    float& c0, float& c1, float& c2, float& c3,
    unsigned a0, unsigned a1, unsigned a2, unsigned a3,
    unsigned b0, unsigned b1)
{
    asm("mma.sync.aligned.m16n8k8.row.col.f32.tf32.tf32.f32 "
        "{%0,%1,%2,%3},{%4,%5,%6,%7},{%8,%9},{%0,%1,%2,%3};"
        : "+f"(c0), "+f"(c1), "+f"(c2), "+f"(c3)
        : "r"(a0), "r"(a1), "r"(a2), "r"(a3), "r"(b0), "r"(b1));
}

__device__ __forceinline__ unsigned long long pk2(float x, float y) {
    unsigned long long r;
    asm("mov.b64 %0, {%1, %2};" : "=l"(r) : "f"(x), "f"(y));
    return r;
}
__device__ __forceinline__ void fma2(unsigned long long &c, unsigned long long a, unsigned long long b) {
    asm("fma.rn.f32x2 %0, %1, %2, %0;" : "+l"(c) : "l"(a), "l"(b));
}
__device__ __forceinline__ void mul2(unsigned long long &c, unsigned long long a, unsigned long long b) {
    asm("mul.rn.f32x2 %0, %1, %2;" : "=l"(c) : "l"(a), "l"(b));
}
__device__ __forceinline__ float2 up2(unsigned long long v) {
    float2 f;
    asm("mov.b64 {%0, %1}, %2;" : "=f"(f.x), "=f"(f.y) : "l"(v));
    return f;
}

// ---------------- fused prologue: gather x0 + zero agg + zero cnt --------------
__global__ void k_gather(const float* __restrict__ emb, const int* __restrict__ ids) {
    int i = blockIdx.x * blockDim.x + threadIdx.x;   // over NN*32 float4
    int row = i >> 5, c = i & 31;
    int nid = ids[row];
    ((float4*)g_x0)[i]  = ((const float4*)emb)[nid * 32 + c];
    ((float4*)g_agg)[i] = make_float4(0.f, 0.f, 0.f, 0.f);
    if (blockIdx.x == 0 && threadIdx.x < NRELC) g_cnt[threadIdx.x] = 0;
}

// histogram with shared-memory aggregation: global atomics drop 131072 -> ~11k
__global__ void __launch_bounds__(512) k_hist(const int* __restrict__ et) {
    __shared__ int sh[NRELC];
    for (int i = threadIdx.x; i < NRELC; i += 512) sh[i] = 0;
    __syncthreads();
    int stride = gridDim.x * 512;
    for (int i = blockIdx.x * 512 + threadIdx.x; i < EE; i += stride)
        atomicAdd(&sh[et[i]], 1);
    __syncthreads();
    for (int i = threadIdx.x; i < NRELC; i += 512)
        if (sh[i]) atomicAdd(&g_cnt[i], sh[i]);
}

// parallel scan over 90 relation counts (128-thread Hillis-Steele)
__global__ void k_scan() {
    __shared__ int s[128];
    int t = threadIdx.x;
    int v = (t < NRELC) ? g_cnt[t] : 0;
    s[t] = v;
    __syncthreads();
    #pragma unroll
    for (int off = 1; off < 128; off <<= 1) {
        int x = (t >= off) ? s[t - off] : 0;
        __syncthreads();
        s[t] += x;
        __syncthreads();
    }
    if (t < NRELC) {
        int excl = s[t] - v;
        g_off[t] = excl;
        g_cur[t] = excl;
    }
    if (t == NRELC - 1) g_off[NRELC] = s[t];
}

// counting-sort scatter with block-level aggregation:
// each block ranks its 2048 edges via SMEM atomics, reserves per-relation
// ranges with ONE global atomic per (block, relation), then scatters.
#define PCH 2048
#define PT  512
__global__ void __launch_bounds__(PT) k_permute(
    const int* __restrict__ et,
    const int* __restrict__ src, const int* __restrict__ dst,
    const float* __restrict__ norm)
{
    __shared__ int scnt[NRELC];
    __shared__ int sbase[NRELC];
    int tid = threadIdx.x;
    int base = blockIdx.x * PCH;
    for (int i = tid; i < NRELC; i += PT) scnt[i] = 0;
    __syncthreads();

    int rel[PCH / PT], rank[PCH / PT];
    #pragma unroll
    for (int k = 0; k < PCH / PT; k++) {
        int e = base + k * PT + tid;
        int r = et[e];
        rel[k] = r;
        rank[k] = atomicAdd(&scnt[r], 1);
    }
    __syncthreads();
    for (int i = tid; i < NRELC; i += PT) {
        int c = scnt[i];
        sbase[i] = c ? atomicAdd(&g_cur[i], c) : 0;
    }
    __syncthreads();
    #pragma unroll
    for (int k = 0; k < PCH / PT; k++) {
        int e = base + k * PT + tid;
        int p = sbase[rel[k]] + rank[k];
        g_srcS[p]  = src[e];
        g_dstS[p]  = dst[e];
        g_normS[p] = norm[e];
    }
}

// ---------------- RGCN edge message kernel (sorted by relation) ----------------
// grid: (CHUNKS, NREL), block 256 = 8 warps, 1 warp per edge.
// W hoisted to registers (packed f32x2); per-lane direct x loads (no shuffles).
__global__ void __launch_bounds__(256) k_edge(
    const float* __restrict__ x, const float* __restrict__ W,
    float* __restrict__ agg)
{
    __shared__ float Ws[NBC * SIC * SIC];   // 8 KB
    int rel = blockIdx.y;
    int start = g_off[rel], end = g_off[rel + 1];
    if (start == end) return;

    for (int i = threadIdx.x; i < NBC * SIC * SIC; i += 256)
        Ws[i] = W[rel * NBC * SIC * SIC + i];
    __syncthreads();

    int warp = threadIdx.x >> 5, lane = threadIdx.x & 31;
    int b = lane >> 2;                    // block-diag block 0..7
    int j = (lane & 3) << 2;              // output col base within block

    unsigned long long wlo[SIC], whi[SIC];
    #pragma unroll
    for (int i = 0; i < SIC; i++) {
        float4 wv = *(const float4*)&Ws[b * 256 + i * SIC + j];
        wlo[i] = pk2(wv.x, wv.y);
        whi[i] = pk2(wv.z, wv.w);
    }

    for (int idx = start + blockIdx.x * 8 + warp; idx < end; idx += gridDim.x * 8) {
        int s = g_srcS[idx], d = g_dstS[idx];
        float nrm = g_normS[idx];
        const float4* xr = (const float4*)(x + (long)s * HH + b * SIC);
        float4 xa = xr[0], xb = xr[1], xc = xr[2], xd = xr[3];
        float xs[16] = {xa.x, xa.y, xa.z, xa.w, xb.x, xb.y, xb.z, xb.w,
                        xc.x, xc.y, xc.z, xc.w, xd.x, xd.y, xd.z, xd.w};

        unsigned long long alo = 0ull, ahi = 0ull;
        #pragma unroll
        for (int i = 0; i < SIC; i++) {
            unsigned long long xi2 = pk2(xs[i], xs[i]);
            fma2(alo, xi2, wlo[i]);
            fma2(ahi, xi2, whi[i]);
        }
        unsigned long long n2 = pk2(nrm, nrm);
        mul2(alo, alo, n2);
        mul2(ahi, ahi, n2);
        float2 lo = up2(alo), hi = up2(ahi);
        atomicAdd((float4*)(agg + (long)d * HH + b * SIC + j),
                  make_float4(lo.x, lo.y, hi.x, hi.y));
    }
}

// ---------------- C[8192,HB] = A[8192,128] @ B[128,HB] via tf32 mma ----------
// tile 128x64, 8 warps 4(m)x2(n), register-prefetch pipeline over 4 K-chunks.
// Optional: addM (+ clear it in place), bias, relu; extra grid.y row zeroes zbuf.
__global__ void __launch_bounds__(256) k_gemm_mma(
    const float* __restrict__ A, const float* __restrict__ B,
    float* __restrict__ C, int HB,
    float* __restrict__ addM, const float* __restrict__ bias,
    int relu, int clearAddM, float* __restrict__ zbuf)
{
    if (zbuf != nullptr && blockIdx.y == (int)gridDim.y - 1) {
        for (int i = blockIdx.x * 256 + threadIdx.x; i < HH * HH / 4; i += gridDim.x * 256)
            ((float4*)zbuf)[i] = make_float4(0.f, 0.f, 0.f, 0.f);
        return;
    }
    __shared__ unsigned As[128][36];
    __shared__ unsigned Bs[32][72];
    int bm = blockIdx.x * 128;
    int bn = blockIdx.y * 64;
    int tid = threadIdx.x, w = tid >> 5, lane = tid & 31;
    int g = lane >> 2, tg = lane & 3;
    int wm = (w >> 1) * 32, wn = (w & 1) * 32;

    int arow = tid >> 3, ac = (tid & 7) << 2;
    int brow = tid >> 4, bc = (tid & 15) << 2;

    float4 ra[4], rb[2];
    #pragma unroll
    for (int it = 0; it < 4; it++)
        ra[it] = *(const float4*)&A[(long)(bm + arow + it * 32) * HH + ac];
    #pragma unroll
    for (int it = 0; it < 2; it++)
        rb[it] = *(const float4*)&B[(long)(brow + it * 16) * HB + bn + bc];

    float acc[2][4][4];
    #pragma unroll
    for (int mt = 0; mt < 2; mt++)
        #pragma unroll
        for (int nt = 0; nt < 4; nt++)
            #pragma unroll
            for (int q = 0; q < 4; q++) acc[mt][nt][q] = 0.f;

    for (int kc = 0; kc < 4; kc++) {
        #pragma unroll
        for (int it = 0; it < 4; it++) {
            int r = arow + it * 32;
            As[r][ac + 0] = f2tf(ra[it].x); As[r][ac + 1] = f2tf(ra[it].y);
            As[r][ac + 2] = f2tf(ra[it].z); As[r][ac + 3] = f2tf(ra[it].w);
        }
        #pragma unroll
        for (int it = 0; it < 2; it++) {
            int r = brow + it * 16;
            Bs[r][bc + 0] = f2tf(rb[it].x); Bs[r][bc + 1] = f2tf(rb[it].y);
            Bs[r][bc + 2] = f2tf(rb[it].z); Bs[r][bc + 3] = f2tf(rb[it].w);
        }
        __syncthreads();
        if (kc < 3) {
            int k0 = (kc + 1) * 32;
            #pragma unroll
            for (int it = 0; it < 4; it++)
                ra[it] = *(const float4*)&A[(long)(bm + arow + it * 32) * HH + k0 + ac];
            #pragma unroll
            for (int it = 0; it < 2; it++)
                rb[it] = *(const float4*)&B[(long)(k0 + brow + it * 16) * HB + bn + bc];
        }
        #pragma unroll
        for (int ks = 0; ks < 4; ks++) {
            int kk = ks * 8;
            unsigned b0[4], b1[4];
            #pragma unroll
            for (int nt = 0; nt < 4; nt++) {
                b0[nt] = Bs[kk + tg][wn + nt * 8 + g];
                b1[nt] = Bs[kk + tg + 4][wn + nt * 8 + g];
            }
            #pragma unroll
            for (int mt = 0; mt < 2; mt++) {
                int rbse = wm + mt * 16;
                unsigned a0 = As[rbse + g][kk + tg];
                unsigned a1 = As[rbse + g + 8][kk + tg];
                unsigned a2 = As[rbse + g][kk + tg + 4];
                unsigned a3 = As[rbse + g + 8][kk + tg + 4];
                #pragma unroll
                for (int nt = 0; nt < 4; nt++)
                    mma_tf32(acc[mt][nt][0], acc[mt][nt][1], acc[mt][nt][2], acc[mt][nt][3],
                             a0, a1, a2, a3, b0[nt], b1[nt]);
            }
        }
        __syncthreads();
    }

    #pragma unroll
    for (int mt = 0; mt < 2; mt++) {
        #pragma unroll
        for (int nt = 0; nt < 4; nt++) {
            int col = bn + wn + nt * 8 + 2 * tg;
            float bx = 0.f, by = 0.f;
            if (bias) { bx = bias[col]; by = bias[col + 1]; }
            #pragma unroll
            for (int h = 0; h < 2; h++) {
                long row = bm + wm + mt * 16 + g + h * 8;
                float vx = acc[mt][nt][2 * h] + bx;
                float vy = acc[mt][nt][2 * h + 1] + by;
                if (addM) {
                    float2 m = *(const float2*)&addM[row * HB + col];
                    vx += m.x; vy += m.y;
                    if (clearAddM)
                        *(float2*)&addM[row * HB + col] = make_float2(0.f, 0.f);
                }
                if (relu) { vx = fmaxf(vx, 0.f); vy = fmaxf(vy, 0.f); }
                *(float2*)&C[row * HB + col] = make_float2(vx, vy);
            }
        }
    }
}

// ---------------- fused VAE head: z = (h2@Wz+bz)[:,:128] + exp((h2@Wz+bz)[:,128:])*eps
__global__ void __launch_bounds__(256) k_gemm_z(
    const float* __restrict__ A, const float* __restrict__ B,   // B = Wz [128][256]
    const float* __restrict__ bz, const float* __restrict__ eps)
{
    __shared__ unsigned As[128][36];
    __shared__ unsigned Bs[2][32][72];
    int bm = blockIdx.x * 128;
    int bn = blockIdx.y * 64;
    int tid = threadIdx.x, w = tid >> 5, lane = tid & 31;
    int g = lane >> 2, tg = lane & 3;
    int wm = (w >> 1) * 32, wn = (w & 1) * 32;

    int arow = tid >> 3, ac = (tid & 7) << 2;
    int brow = tid >> 4, bc = (tid & 15) << 2;

    float4 ra[4], rb[2][2];
    #pragma unroll
    for (int it = 0; it < 4; it++)
        ra[it] = *(const float4*)&A[(long)(bm + arow + it * 32) * HH + ac];
    #pragma unroll
    for (int t = 0; t < 2; t++)
        #pragma unroll
        for (int it = 0; it < 2; it++)
            rb[t][it] = *(const float4*)&B[(long)(brow + it * 16) * 256 + bn + t * 128 + bc];

    float acc[2][2][4][4];
    #pragma unroll
    for (int t = 0; t < 2; t++)
        #pragma unroll
        for (int mt = 0; mt < 2; mt++)
            #pragma unroll
            for (int nt = 0; nt < 4; nt++)
                #pragma unroll
                for (int q = 0; q < 4; q++) acc[t][mt][nt][q] = 0.f;

    for (int kc = 0; kc < 4; kc++) {
        #pragma unroll
        for (int it = 0; it < 4; it++) {
            int r = arow + it * 32;
            As[r][ac + 0] = f2tf(ra[it].x); As[r][ac + 1] = f2tf(ra[it].y);
            As[r][ac + 2] = f2tf(ra[it].z); As[r][ac + 3] = f2tf(ra[it].w);
        }
        #pragma unroll
        for (int t = 0; t < 2; t++)
            #pragma unroll
            for (int it = 0; it < 2; it++) {
                int r = brow + it * 16;
                Bs[t][r][bc + 0] = f2tf(rb[t][it].x); Bs[t][r][bc + 1] = f2tf(rb[t][it].y);
                Bs[t][r][bc + 2] = f2tf(rb[t][it].z); Bs[t][r][bc + 3] = f2tf(rb[t][it].w);
            }
        __syncthreads();
        if (kc < 3) {
            int k0 = (kc + 1) * 32;
            #pragma unroll
            for (int it = 0; it < 4; it++)
                ra[it] = *(const float4*)&A[(long)(bm + arow + it * 32) * HH + k0 + ac];
            #pragma unroll
            for (int t = 0; t < 2; t++)
                #pragma unroll
                for (int it = 0; it < 2; it++)
                    rb[t][it] = *(const float4*)&B[(long)(k0 + brow + it * 16) * 256 + bn + t * 128 + bc];
        }
        #pragma unroll
        for (int ks = 0; ks < 4; ks++) {
            int kk = ks * 8;
            #pragma unroll
            for (int mt = 0; mt < 2; mt++) {
                int rbse = wm + mt * 16;
                unsigned a0 = As[rbse + g][kk + tg];
                unsigned a1 = As[rbse + g + 8][kk + tg];
                unsigned a2 = As[rbse + g][kk + tg + 4];
                unsigned a3 = As[rbse + g + 8][kk + tg + 4];
                #pragma unroll
                for (int t = 0; t < 2; t++)
                    #pragma unroll
                    for (int nt = 0; nt < 4; nt++) {
                        unsigned b0 = Bs[t][kk + tg][wn + nt * 8 + g];
                        unsigned b1 = Bs[t][kk + tg + 4][wn + nt * 8 + g];
                        mma_tf32(acc[t][mt][nt][0], acc[t][mt][nt][1],
                                 acc[t][mt][nt][2], acc[t][mt][nt][3],
                                 a0, a1, a2, a3, b0, b1);
                    }
            }
        }
        __syncthreads();
    }

    #pragma unroll
    for (int mt = 0; mt < 2; mt++) {
        #pragma unroll
        for (int nt = 0; nt < 4; nt++) {
            int zc = bn + wn + nt * 8 + 2 * tg;
            float bm0 = bz[zc],       bm1 = bz[zc + 1];
            float bl0 = bz[zc + 128], bl1 = bz[zc + 129];
            #pragma unroll
            for (int h = 0; h < 2; h++) {
                long row = bm + wm + mt * 16 + g + h * 8;
                float2 e = *(const float2*)&eps[row * HH + zc];
                float z0 = (acc[0][mt][nt][2 * h]     + bm0) + expf(acc[1][mt][nt][2 * h]     + bl0) * e.x;
                float z1 = (acc[0][mt][nt][2 * h + 1] + bm1) + expf(acc[1][mt][nt][2 * h + 1] + bl1) * e.y;
                *(float2*)&g_z[row * HH + zc] = make_float2(z0, z1);
            }
        }
    }
}

// ---------------- S[128,128] += A^T[128,8192] @ B[8192,128], split-K 64 ----------
__global__ void __launch_bounds__(256) k_gemm_red_mma(
    const float* __restrict__ A, const float* __restrict__ B, float* __restrict__ S)
{
    __shared__ unsigned Ak[32][136];   // [k][m]
    __shared__ unsigned Bs[32][136];   // [k][n]
    int k0base = blockIdx.x * 128;
    int tid = threadIdx.x, w = tid >> 5, lane = tid & 31;
    int g = lane >> 2, tg = lane & 3;
    int wm = (w >> 2) * 64, wn = (w & 3) * 32;

    int lrow = tid >> 5, lc = (tid & 31) << 2;

    float4 rA[4], rB[4];
    #pragma unroll
    for (int it = 0; it < 4; it++) {
        rA[it] = *(const float4*)&A[(long)(k0base + lrow + it * 8) * HH + lc];
        rB[it] = *(const float4*)&B[(long)(k0base + lrow + it * 8) * HH + lc];
    }

    float acc[4][4][4];
    #pragma unroll
    for (int mt = 0; mt < 4; mt++)
        #pragma unroll
        for (int nt = 0; nt < 4; nt++)
            #pragma unroll
            for (int q = 0; q < 4; q++) acc[mt][nt][q] = 0.f;

    for (int kc = 0; kc < 4; kc++) {
        #pragma unroll
        for (int it = 0; it < 4; it++) {
            int r = lrow + it * 8;
            Ak[r][lc + 0] = f2tf(rA[it].x); Ak[r][lc + 1] = f2tf(rA[it].y);
            Ak[r][lc + 2] = f2tf(rA[it].z); Ak[r][lc + 3] = f2tf(rA[it].w);
            Bs[r][lc + 0] = f2tf(rB[it].x); Bs[r][lc + 1] = f2tf(rB[it].y);
            Bs[r][lc + 2] = f2tf(rB[it].z); Bs[r][lc + 3] = f2tf(rB[it].w);
        }
        __syncthreads();
        if (kc < 3) {
            int k0 = k0base + (kc + 1) * 32;
            #pragma unroll
            for (int it = 0; it < 4; it++) {
                rA[it] = *(const float4*)&A[(long)(k0 + lrow + it * 8) * HH + lc];
                rB[it] = *(const float4*)&B[(long)(k0 + lrow + it * 8) * HH + lc];
            }
        }
        #pragma unroll
        for (int ks = 0; ks < 4; ks++) {
            int kk = ks * 8;
            unsigned b0[4], b1[4];
            #pragma unroll
            for (int nt = 0; nt < 4; nt++) {
                b0[nt] = Bs[kk + tg][wn + nt * 8 + g];
                b1[nt] = Bs[kk + tg + 4][wn + nt * 8 + g];
            }
            #pragma unroll
            for (int mt = 0; mt < 4; mt++) {
                int mb = wm + mt * 16;
                unsigned a0 = Ak[kk + tg][mb + g];
                unsigned a1 = Ak[kk + tg][mb + g + 8];
                unsigned a2 = Ak[kk + tg + 4][mb + g];
                unsigned a3 = Ak[kk + tg + 4][mb + g + 8];
                #pragma unroll
                for (int nt = 0; nt < 4; nt++)
                    mma_tf32(acc[mt][nt][0], acc[mt][nt][1], acc[mt][nt][2], acc[mt][nt][3],
                             a0, a1, a2, a3, b0[nt], b1[nt]);
            }
        }
        __syncthreads();
    }

    #pragma unroll
    for (int mt = 0; mt < 4; mt++)
        #pragma unroll
        for (int nt = 0; nt < 4; nt++) {
            int col = wn + nt * 8 + 2 * tg;
            #pragma unroll
            for (int h = 0; h < 2; h++) {
                int row = wm + mt * 16 + g + h * 8;
                atomicAdd((float2*)&S[row * HH + col],
                          make_float2(acc[mt][nt][2 * h], acc[mt][nt][2 * h + 1]));
            }
        }
}

// ---------------- launch ----------------
extern "C" void kernel_launch(void* const* d_in, const int* in_sizes, int n_in,
                              void* d_out, int out_size) {
    (void)in_sizes; (void)n_in; (void)out_size;
    const int*   node_ids = (const int*)  d_in[0];
    const int*   src      = (const int*)  d_in[1];
    const int*   dst      = (const int*)  d_in[2];
    const int*   et       = (const int*)  d_in[3];
    const float* norm     = (const float*)d_in[4];
    const float* eps      = (const float*)d_in[5];
    const float* emb      = (const float*)d_in[6];
    const float* W0       = (const float*)d_in[7];
    const float* loop0    = (const float*)d_in[8];
    const float* b0       = (const float*)d_in[9];
    const float* W1       = (const float*)d_in[10];
    const float* loop1    = (const float*)d_in[11];
    const float* b1       = (const float*)d_in[12];
    const float* Wz       = (const float*)d_in[13];
    const float* bz       = (const float*)d_in[14];
    const float* Wi       = (const float*)d_in[15];
    const float* bi       = (const float*)d_in[16];
    const float* hbi      = (const float*)d_in[17];
    const float* Wo       = (const float*)d_in[18];
    const float* bo       = (const float*)d_in[19];
    const float* hbo      = (const float*)d_in[20];
    float* out = (float*)d_out;

    float *p_x0, *p_h1, *p_h2, *p_agg, *p_z, *p_M, *p_h3, *p_S;
    cudaGetSymbolAddress((void**)&p_x0,  g_x0);
    cudaGetSymbolAddress((void**)&p_h1,  g_h1);
    cudaGetSymbolAddress((void**)&p_h2,  g_h2);
    cudaGetSymbolAddress((void**)&p_agg, g_agg);
    cudaGetSymbolAddress((void**)&p_z,   g_z);
    cudaGetSymbolAddress((void**)&p_M,   g_M);
    cudaGetSymbolAddress((void**)&p_h3,  g_h3);
    cudaGetSymbolAddress((void**)&p_S,   g_S);

    // prologue: gather x0 (+ zero agg, zero cnt), then counting sort by relation
    k_gather<<<NN * 32 / 256, 256>>>(emb, node_ids);
    k_hist<<<128, 512>>>(et);
    k_scan<<<1, 128>>>();
    k_permute<<<EE / PCH, PT>>>(et, src, dst, norm);

    // RGCN layer 0: h1 = relu(agg + b0 + x0 @ loop0); epilogue clears agg for layer 1
    k_edge<<<dim3(12, NRELC), 256>>>(p_x0, W0, p_agg);
    k_gemm_mma<<<dim3(64, 2), 256>>>(p_x0, loop0, p_h1, HH, p_agg, b0, 1, 1, nullptr);

    // RGCN layer 1: h2 = agg + b1 + h1 @ loop1
    k_edge<<<dim3(12, NRELC), 256>>>(p_h1, W1, p_agg);
    k_gemm_mma<<<dim3(64, 2), 256>>>(p_h1, loop1, p_h2, HH, p_agg, b1, 0, 0, nullptr);

    // VAE head fused: z = mean + exp(log_std)*eps
    k_gemm_z<<<dim3(64, 2), 256>>>(p_h2, Wz, bz, eps);

    // decode 1: h3 = z @ (z^T @ (z@Wi + bi + x0)) + hbi   [R@M == z(z^T M)]
    k_gemm_mma<<<dim3(64, 3), 256>>>(p_z, Wi, p_M, HH, p_x0, bi, 0, 0, p_S); // extra row zeroes S
    k_gemm_red_mma<<<64, 256>>>(p_z, p_M, p_S);
    k_gemm_mma<<<dim3(64, 2), 256>>>(p_z, p_S, p_h3, HH, nullptr, hbi, 0, 0, nullptr);

    // decode 2: out = h3 @ (h3^T @ (h3@Wo + bo + x0)) + hbo
    k_gemm_mma<<<dim3(64, 3), 256>>>(p_h3, Wo, p_M, HH, p_x0, bo, 0, 0, p_S);
    k_gemm_red_mma<<<64, 256>>>(p_h3, p_M, p_S);
    k_gemm_mma<<<dim3(64, 2), 256>>>(p_h3, p_S, out, HH, nullptr, hbo, 0, 0, nullptr);
}

// round 17
// speedup vs baseline: 2.2989x; 1.1344x over previous
#include <cuda_runtime.h>

#define NN   8192
#define HH   128
#define EE   131072
#define NRELC 90
#define NBC  8
#define SIC  16

// ---------------- device scratch (no allocations allowed) ----------------
__device__ float g_x0[NN*HH];
__device__ float g_h1[NN*HH];
__device__ float g_h2[NN*HH];
__device__ float g_agg[NN*HH];
__device__ float g_z[NN*HH];
__device__ float g_M[NN*HH];
__device__ float g_h3[NN*HH];
__device__ float g_S[HH*HH];
__device__ int   g_srcS[EE];
__device__ int   g_dstS[EE];
__device__ float g_normS[EE];
__device__ int   g_cnt[NRELC];
__device__ int   g_off[NRELC+1];
__device__ int   g_cur[NRELC];

// ---------------- helpers ----------------
__device__ __forceinline__ unsigned f2tf(float f) {
    unsigned u;
    asm("cvt.rna.tf32.f32 %0, %1;" : "=r"(u) : "f"(f));
    return u;
}

__device__ __forceinline__ void mma_tf32(
    float& c0, float& c1, float& c2, float& c3,
    unsigned a0, unsigned a1, unsigned a2, unsigned a3,
    unsigned b0, unsigned b1)
{
    asm("mma.sync.aligned.m16n8k8.row.col.f32.tf32.tf32.f32 "
        "{%0,%1,%2,%3},{%4,%5,%6,%7},{%8,%9},{%0,%1,%2,%3};"
        : "+f"(c0), "+f"(c1), "+f"(c2), "+f"(c3)
        : "r"(a0), "r"(a1), "r"(a2), "r"(a3), "r"(b0), "r"(b1));
}

__device__ __forceinline__ unsigned long long pk2(float x, float y) {
    unsigned long long r;
    asm("mov.b64 %0, {%1, %2};" : "=l"(r) : "f"(x), "f"(y));
    return r;
}
__device__ __forceinline__ void fma2(unsigned long long &c, unsigned long long a, unsigned long long b) {
    asm("fma.rn.f32x2 %0, %1, %2, %0;" : "+l"(c) : "l"(a), "l"(b));
}
__device__ __forceinline__ void mul2(unsigned long long &c, unsigned long long a, unsigned long long b) {
    asm("mul.rn.f32x2 %0, %1, %2;" : "=l"(c) : "l"(a), "l"(b));
}
__device__ __forceinline__ float2 up2(unsigned long long v) {
    float2 f;
    asm("mov.b64 {%0, %1}, %2;" : "=f"(f.x), "=f"(f.y) : "l"(v));
    return f;
}

// ---------------- fused prologue: gather x0 + zero agg + zero cnt --------------
__global__ void k_gather(const float* __restrict__ emb, const int* __restrict__ ids) {
    int i = blockIdx.x * blockDim.x + threadIdx.x;   // over NN*32 float4
    int row = i >> 5, c = i & 31;
    int nid = ids[row];
    ((float4*)g_x0)[i]  = ((const float4*)emb)[nid * 32 + c];
    ((float4*)g_agg)[i] = make_float4(0.f, 0.f, 0.f, 0.f);
    if (blockIdx.x == 0 && threadIdx.x < NRELC) g_cnt[threadIdx.x] = 0;
}

// histogram with shared-memory aggregation: global atomics drop 131072 -> ~11k
__global__ void __launch_bounds__(512) k_hist(const int* __restrict__ et) {
    __shared__ int sh[NRELC];
    for (int i = threadIdx.x; i < NRELC; i += 512) sh[i] = 0;
    __syncthreads();
    int stride = gridDim.x * 512;
    for (int i = blockIdx.x * 512 + threadIdx.x; i < EE; i += stride)
        atomicAdd(&sh[et[i]], 1);
    __syncthreads();
    for (int i = threadIdx.x; i < NRELC; i += 512)
        if (sh[i]) atomicAdd(&g_cnt[i], sh[i]);
}

// parallel scan over 90 relation counts (128-thread Hillis-Steele)
__global__ void k_scan() {
    __shared__ int s[128];
    int t = threadIdx.x;
    int v = (t < NRELC) ? g_cnt[t] : 0;
    s[t] = v;
    __syncthreads();
    #pragma unroll
    for (int off = 1; off < 128; off <<= 1) {
        int x = (t >= off) ? s[t - off] : 0;
        __syncthreads();
        s[t] += x;
        __syncthreads();
    }
    if (t < NRELC) {
        int excl = s[t] - v;
        g_off[t] = excl;
        g_cur[t] = excl;
    }
    if (t == NRELC - 1) g_off[NRELC] = s[t];
}

// counting-sort scatter with block-level aggregation (128 blocks x 1024 edges)
#define PCH 1024
#define PT  512
__global__ void __launch_bounds__(PT) k_permute(
    const int* __restrict__ et,
    const int* __restrict__ src, const int* __restrict__ dst,
    const float* __restrict__ norm)
{
    __shared__ int scnt[NRELC];
    __shared__ int sbase[NRELC];
    int tid = threadIdx.x;
    int base = blockIdx.x * PCH;
    for (int i = tid; i < NRELC; i += PT) scnt[i] = 0;
    __syncthreads();

    int rel[PCH / PT], rank[PCH / PT];
    #pragma unroll
    for (int k = 0; k < PCH / PT; k++) {
        int e = base + k * PT + tid;
        int r = et[e];
        rel[k] = r;
        rank[k] = atomicAdd(&scnt[r], 1);
    }
    __syncthreads();
    for (int i = tid; i < NRELC; i += PT) {
        int c = scnt[i];
        sbase[i] = c ? atomicAdd(&g_cur[i], c) : 0;
    }
    __syncthreads();
    #pragma unroll
    for (int k = 0; k < PCH / PT; k++) {
        int e = base + k * PT + tid;
        int p = sbase[rel[k]] + rank[k];
        g_srcS[p]  = src[e];
        g_dstS[p]  = dst[e];
        g_normS[p] = norm[e];
    }
}

// ---------------- RGCN edge message kernel (sorted by relation) ----------------
// grid: (CHUNKS, NREL), block 256 = 8 warps, 1 warp per edge.
// Software-pipelined: edge i+1's meta + x row are prefetched while computing i.
__global__ void __launch_bounds__(256) k_edge(
    const float* __restrict__ x, const float* __restrict__ W,
    float* __restrict__ agg)
{
    __shared__ float Ws[NBC * SIC * SIC];   // 8 KB
    int rel = blockIdx.y;
    int start = g_off[rel], end = g_off[rel + 1];
    if (start == end) return;

    for (int i = threadIdx.x; i < NBC * SIC * SIC; i += 256)
        Ws[i] = W[rel * NBC * SIC * SIC + i];
    __syncthreads();

    int warp = threadIdx.x >> 5, lane = threadIdx.x & 31;
    int b = lane >> 2;                    // block-diag block 0..7
    int j = (lane & 3) << 2;              // output col base within block

    unsigned long long wlo[SIC], whi[SIC];
    #pragma unroll
    for (int i = 0; i < SIC; i++) {
        float4 wv = *(const float4*)&Ws[b * 256 + i * SIC + j];
        wlo[i] = pk2(wv.x, wv.y);
        whi[i] = pk2(wv.z, wv.w);
    }

    const int step = gridDim.x * 8;
    int idx = start + blockIdx.x * 8 + warp;

    int s = 0, d = 0; float nrm = 0.f;
    float4 X0, X1, X2, X3;
    if (idx < end) {
        s = g_srcS[idx]; d = g_dstS[idx]; nrm = g_normS[idx];
        const float4* xr = (const float4*)(x + (long)s * HH + b * SIC);
        X0 = xr[0]; X1 = xr[1]; X2 = xr[2]; X3 = xr[3];
    }
    while (idx < end) {
        int nidx = idx + step;
        int ns = 0, nd = 0; float nn = 0.f;
        float4 N0, N1, N2, N3;
        if (nidx < end) {
            ns = g_srcS[nidx]; nd = g_dstS[nidx]; nn = g_normS[nidx];
            const float4* xr = (const float4*)(x + (long)ns * HH + b * SIC);
            N0 = xr[0]; N1 = xr[1]; N2 = xr[2]; N3 = xr[3];
        }

        float xs[16] = {X0.x, X0.y, X0.z, X0.w, X1.x, X1.y, X1.z, X1.w,
                        X2.x, X2.y, X2.z, X2.w, X3.x, X3.y, X3.z, X3.w};
        unsigned long long alo = 0ull, ahi = 0ull;
        #pragma unroll
        for (int i = 0; i < SIC; i++) {
            unsigned long long xi2 = pk2(xs[i], xs[i]);
            fma2(alo, xi2, wlo[i]);
            fma2(ahi, xi2, whi[i]);
        }
        unsigned long long n2 = pk2(nrm, nrm);
        mul2(alo, alo, n2);
        mul2(ahi, ahi, n2);
        float2 lo = up2(alo), hi = up2(ahi);
        atomicAdd((float4*)(agg + (long)d * HH + b * SIC + j),
                  make_float4(lo.x, lo.y, hi.x, hi.y));

        idx = nidx;
        s = ns; d = nd; nrm = nn;
        X0 = N0; X1 = N1; X2 = N2; X3 = N3;
    }
}

// ---------------- C[8192,HB] = A[8192,128] @ B[128,HB] via tf32 mma ----------
// tile 128x64, 8 warps 4(m)x2(n), register-prefetch pipeline over 4 K-chunks.
// Optional: addM (+ clear it in place), bias, relu; extra grid.y row zeroes zbuf.
__global__ void __launch_bounds__(256) k_gemm_mma(
    const float* __restrict__ A, const float* __restrict__ B,
    float* __restrict__ C, int HB,
    float* __restrict__ addM, const float* __restrict__ bias,
    int relu, int clearAddM, float* __restrict__ zbuf)
{
    if (zbuf != nullptr && blockIdx.y == (int)gridDim.y - 1) {
        for (int i = blockIdx.x * 256 + threadIdx.x; i < HH * HH / 4; i += gridDim.x * 256)
            ((float4*)zbuf)[i] = make_float4(0.f, 0.f, 0.f, 0.f);
        return;
    }
    __shared__ unsigned As[128][36];
    __shared__ unsigned Bs[32][72];
    int bm = blockIdx.x * 128;
    int bn = blockIdx.y * 64;
    int tid = threadIdx.x, w = tid >> 5, lane = tid & 31;
    int g = lane >> 2, tg = lane & 3;
    int wm = (w >> 1) * 32, wn = (w & 1) * 32;

    int arow = tid >> 3, ac = (tid & 7) << 2;
    int brow = tid >> 4, bc = (tid & 15) << 2;

    float4 ra[4], rb[2];
    #pragma unroll
    for (int it = 0; it < 4; it++)
        ra[it] = *(const float4*)&A[(long)(bm + arow + it * 32) * HH + ac];
    #pragma unroll
    for (int it = 0; it < 2; it++)
        rb[it] = *(const float4*)&B[(long)(brow + it * 16) * HB + bn + bc];

    float acc[2][4][4];
    #pragma unroll
    for (int mt = 0; mt < 2; mt++)
        #pragma unroll
        for (int nt = 0; nt < 4; nt++)
            #pragma unroll
            for (int q = 0; q < 4; q++) acc[mt][nt][q] = 0.f;

    for (int kc = 0; kc < 4; kc++) {
        #pragma unroll
        for (int it = 0; it < 4; it++) {
            int r = arow + it * 32;
            As[r][ac + 0] = f2tf(ra[it].x); As[r][ac + 1] = f2tf(ra[it].y);
            As[r][ac + 2] = f2tf(ra[it].z); As[r][ac + 3] = f2tf(ra[it].w);
        }
        #pragma unroll
        for (int it = 0; it < 2; it++) {
            int r = brow + it * 16;
            Bs[r][bc + 0] = f2tf(rb[it].x); Bs[r][bc + 1] = f2tf(rb[it].y);
            Bs[r][bc + 2] = f2tf(rb[it].z); Bs[r][bc + 3] = f2tf(rb[it].w);
        }
        __syncthreads();
        if (kc < 3) {
            int k0 = (kc + 1) * 32;
            #pragma unroll
            for (int it = 0; it < 4; it++)
                ra[it] = *(const float4*)&A[(long)(bm + arow + it * 32) * HH + k0 + ac];
            #pragma unroll
            for (int it = 0; it < 2; it++)
                rb[it] = *(const float4*)&B[(long)(k0 + brow + it * 16) * HB + bn + bc];
        }
        #pragma unroll
        for (int ks = 0; ks < 4; ks++) {
            int kk = ks * 8;
            unsigned b0[4], b1[4];
            #pragma unroll
            for (int nt = 0; nt < 4; nt++) {
                b0[nt] = Bs[kk + tg][wn + nt * 8 + g];
                b1[nt] = Bs[kk + tg + 4][wn + nt * 8 + g];
            }
            #pragma unroll
            for (int mt = 0; mt < 2; mt++) {
                int rbse = wm + mt * 16;
                unsigned a0 = As[rbse + g][kk + tg];
                unsigned a1 = As[rbse + g + 8][kk + tg];
                unsigned a2 = As[rbse + g][kk + tg + 4];
                unsigned a3 = As[rbse + g + 8][kk + tg + 4];
                #pragma unroll
                for (int nt = 0; nt < 4; nt++)
                    mma_tf32(acc[mt][nt][0], acc[mt][nt][1], acc[mt][nt][2], acc[mt][nt][3],
                             a0, a1, a2, a3, b0[nt], b1[nt]);
            }
        }
        __syncthreads();
    }

    #pragma unroll
    for (int mt = 0; mt < 2; mt++) {
        #pragma unroll
        for (int nt = 0; nt < 4; nt++) {
            int col = bn + wn + nt * 8 + 2 * tg;
            float bx = 0.f, by = 0.f;
            if (bias) { bx = bias[col]; by = bias[col + 1]; }
            #pragma unroll
            for (int h = 0; h < 2; h++) {
                long row = bm + wm + mt * 16 + g + h * 8;
                float vx = acc[mt][nt][2 * h] + bx;
                float vy = acc[mt][nt][2 * h + 1] + by;
                if (addM) {
                    float2 m = *(const float2*)&addM[row * HB + col];
                    vx += m.x; vy += m.y;
                    if (clearAddM)
                        *(float2*)&addM[row * HB + col] = make_float2(0.f, 0.f);
                }
                if (relu) { vx = fmaxf(vx, 0.f); vy = fmaxf(vy, 0.f); }
                *(float2*)&C[row * HB + col] = make_float2(vx, vy);
            }
        }
    }
}

// ---------------- fused VAE head: z = (h2@Wz+bz)[:,:128] + exp((h2@Wz+bz)[:,128:])*eps
__global__ void __launch_bounds__(256) k_gemm_z(
    const float* __restrict__ A, const float* __restrict__ B,   // B = Wz [128][256]
    const float* __restrict__ bz, const float* __restrict__ eps)
{
    __shared__ unsigned As[128][36];
    __shared__ unsigned Bs[2][32][72];
    int bm = blockIdx.x * 128;
    int bn = blockIdx.y * 64;
    int tid = threadIdx.x, w = tid >> 5, lane = tid & 31;
    int g = lane >> 2, tg = lane & 3;
    int wm = (w >> 1) * 32, wn = (w & 1) * 32;

    int arow = tid >> 3, ac = (tid & 7) << 2;
    int brow = tid >> 4, bc = (tid & 15) << 2;

    float4 ra[4], rb[2][2];
    #pragma unroll
    for (int it = 0; it < 4; it++)
        ra[it] = *(const float4*)&A[(long)(bm + arow + it * 32) * HH + ac];
    #pragma unroll
    for (int t = 0; t < 2; t++)
        #pragma unroll
        for (int it = 0; it < 2; it++)
            rb[t][it] = *(const float4*)&B[(long)(brow + it * 16) * 256 + bn + t * 128 + bc];

    float acc[2][2][4][4];
    #pragma unroll
    for (int t = 0; t < 2; t++)
        #pragma unroll
        for (int mt = 0; mt < 2; mt++)
            #pragma unroll
            for (int nt = 0; nt < 4; nt++)
                #pragma unroll
                for (int q = 0; q < 4; q++) acc[t][mt][nt][q] = 0.f;

    for (int kc = 0; kc < 4; kc++) {
        #pragma unroll
        for (int it = 0; it < 4; it++) {
            int r = arow + it * 32;
            As[r][ac + 0] = f2tf(ra[it].x); As[r][ac + 1] = f2tf(ra[it].y);
            As[r][ac + 2] = f2tf(ra[it].z); As[r][ac + 3] = f2tf(ra[it].w);
        }
        #pragma unroll
        for (int t = 0; t < 2; t++)
            #pragma unroll
            for (int it = 0; it < 2; it++) {
                int r = brow + it * 16;
                Bs[t][r][bc + 0] = f2tf(rb[t][it].x); Bs[t][r][bc + 1] = f2tf(rb[t][it].y);
                Bs[t][r][bc + 2] = f2tf(rb[t][it].z); Bs[t][r][bc + 3] = f2tf(rb[t][it].w);
            }
        __syncthreads();
        if (kc < 3) {
            int k0 = (kc + 1) * 32;
            #pragma unroll
            for (int it = 0; it < 4; it++)
                ra[it] = *(const float4*)&A[(long)(bm + arow + it * 32) * HH + k0 + ac];
            #pragma unroll
            for (int t = 0; t < 2; t++)
                #pragma unroll
                for (int it = 0; it < 2; it++)
                    rb[t][it] = *(const float4*)&B[(long)(k0 + brow + it * 16) * 256 + bn + t * 128 + bc];
        }
        #pragma unroll
        for (int ks = 0; ks < 4; ks++) {
            int kk = ks * 8;
            #pragma unroll
            for (int mt = 0; mt < 2; mt++) {
                int rbse = wm + mt * 16;
                unsigned a0 = As[rbse + g][kk + tg];
                unsigned a1 = As[rbse + g + 8][kk + tg];
                unsigned a2 = As[rbse + g][kk + tg + 4];
                unsigned a3 = As[rbse + g + 8][kk + tg + 4];
                #pragma unroll
                for (int t = 0; t < 2; t++)
                    #pragma unroll
                    for (int nt = 0; nt < 4; nt++) {
                        unsigned b0 = Bs[t][kk + tg][wn + nt * 8 + g];
                        unsigned b1 = Bs[t][kk + tg + 4][wn + nt * 8 + g];
                        mma_tf32(acc[t][mt][nt][0], acc[t][mt][nt][1],
                                 acc[t][mt][nt][2], acc[t][mt][nt][3],
                                 a0, a1, a2, a3, b0, b1);
                    }
            }
        }
        __syncthreads();
    }

    #pragma unroll
    for (int mt = 0; mt < 2; mt++) {
        #pragma unroll
        for (int nt = 0; nt < 4; nt++) {
            int zc = bn + wn + nt * 8 + 2 * tg;
            float bm0 = bz[zc],       bm1 = bz[zc + 1];
            float bl0 = bz[zc + 128], bl1 = bz[zc + 129];
            #pragma unroll
            for (int h = 0; h < 2; h++) {
                long row = bm + wm + mt * 16 + g + h * 8;
                float2 e = *(const float2*)&eps[row * HH + zc];
                float z0 = (acc[0][mt][nt][2 * h]     + bm0) + expf(acc[1][mt][nt][2 * h]     + bl0) * e.x;
                float z1 = (acc[0][mt][nt][2 * h + 1] + bm1) + expf(acc[1][mt][nt][2 * h + 1] + bl1) * e.y;
                *(float2*)&g_z[row * HH + zc] = make_float2(z0, z1);
            }
        }
    }
}

// ---------------- S[128,128] += A^T[128,8192] @ B[8192,128], split-K 64 ----------
__global__ void __launch_bounds__(256) k_gemm_red_mma(
    const float* __restrict__ A, const float* __restrict__ B, float* __restrict__ S)
{
    __shared__ unsigned Ak[32][136];   // [k][m]
    __shared__ unsigned Bs[32][136];   // [k][n]
    int k0base = blockIdx.x * 128;
    int tid = threadIdx.x, w = tid >> 5, lane = tid & 31;
    int g = lane >> 2, tg = lane & 3;
    int wm = (w >> 2) * 64, wn = (w & 3) * 32;

    int lrow = tid >> 5, lc = (tid & 31) << 2;

    float4 rA[4], rB[4];
    #pragma unroll
    for (int it = 0; it < 4; it++) {
        rA[it] = *(const float4*)&A[(long)(k0base + lrow + it * 8) * HH + lc];
        rB[it] = *(const float4*)&B[(long)(k0base + lrow + it * 8) * HH + lc];
    }

    float acc[4][4][4];
    #pragma unroll
    for (int mt = 0; mt < 4; mt++)
        #pragma unroll
        for (int nt = 0; nt < 4; nt++)
            #pragma unroll
            for (int q = 0; q < 4; q++) acc[mt][nt][q] = 0.f;

    for (int kc = 0; kc < 4; kc++) {
        #pragma unroll
        for (int it = 0; it < 4; it++) {
            int r = lrow + it * 8;
            Ak[r][lc + 0] = f2tf(rA[it].x); Ak[r][lc + 1] = f2tf(rA[it].y);
            Ak[r][lc + 2] = f2tf(rA[it].z); Ak[r][lc + 3] = f2tf(rA[it].w);
            Bs[r][lc + 0] = f2tf(rB[it].x); Bs[r][lc + 1] = f2tf(rB[it].y);
            Bs[r][lc + 2] = f2tf(rB[it].z); Bs[r][lc + 3] = f2tf(rB[it].w);
        }
        __syncthreads();
        if (kc < 3) {
            int k0 = k0base + (kc + 1) * 32;
            #pragma unroll
            for (int it = 0; it < 4; it++) {
                rA[it] = *(const float4*)&A[(long)(k0 + lrow + it * 8) * HH + lc];
                rB[it] = *(const float4*)&B[(long)(k0 + lrow + it * 8) * HH + lc];
            }
        }
        #pragma unroll
        for (int ks = 0; ks < 4; ks++) {
            int kk = ks * 8;
            unsigned b0[4], b1[4];
            #pragma unroll
            for (int nt = 0; nt < 4; nt++) {
                b0[nt] = Bs[kk + tg][wn + nt * 8 + g];
                b1[nt] = Bs[kk + tg + 4][wn + nt * 8 + g];
            }
            #pragma unroll
            for (int mt = 0; mt < 4; mt++) {
                int mb = wm + mt * 16;
                unsigned a0 = Ak[kk + tg][mb + g];
                unsigned a1 = Ak[kk + tg][mb + g + 8];
                unsigned a2 = Ak[kk + tg + 4][mb + g];
                unsigned a3 = Ak[kk + tg + 4][mb + g + 8];
                #pragma unroll
                for (int nt = 0; nt < 4; nt++)
                    mma_tf32(acc[mt][nt][0], acc[mt][nt][1], acc[mt][nt][2], acc[mt][nt][3],
                             a0, a1, a2, a3, b0[nt], b1[nt]);
            }
        }
        __syncthreads();
    }

    #pragma unroll
    for (int mt = 0; mt < 4; mt++)
        #pragma unroll
        for (int nt = 0; nt < 4; nt++) {
            int col = wn + nt * 8 + 2 * tg;
            #pragma unroll
            for (int h = 0; h < 2; h++) {
                int row = wm + mt * 16 + g + h * 8;
                atomicAdd((float2*)&S[row * HH + col],
                          make_float2(acc[mt][nt][2 * h], acc[mt][nt][2 * h + 1]));
            }
        }
}

// ---------------- launch ----------------
extern "C" void kernel_launch(void* const* d_in, const int* in_sizes, int n_in,
                              void* d_out, int out_size) {
    (void)in_sizes; (void)n_in; (void)out_size;
    const int*   node_ids = (const int*)  d_in[0];
    const int*   src      = (const int*)  d_in[1];
    const int*   dst      = (const int*)  d_in[2];
    const int*   et       = (const int*)  d_in[3];
    const float* norm     = (const float*)d_in[4];
    const float* eps      = (const float*)d_in[5];
    const float* emb      = (const float*)d_in[6];
    const float* W0       = (const float*)d_in[7];
    const float* loop0    = (const float*)d_in[8];
    const float* b0       = (const float*)d_in[9];
    const float* W1       = (const float*)d_in[10];
    const float* loop1    = (const float*)d_in[11];
    const float* b1       = (const float*)d_in[12];
    const float* Wz       = (const float*)d_in[13];
    const float* bz       = (const float*)d_in[14];
    const float* Wi       = (const float*)d_in[15];
    const float* bi       = (const float*)d_in[16];
    const float* hbi      = (const float*)d_in[17];
    const float* Wo       = (const float*)d_in[18];
    const float* bo       = (const float*)d_in[19];
    const float* hbo      = (const float*)d_in[20];
    float* out = (float*)d_out;

    float *p_x0, *p_h1, *p_h2, *p_agg, *p_z, *p_M, *p_h3, *p_S;
    cudaGetSymbolAddress((void**)&p_x0,  g_x0);
    cudaGetSymbolAddress((void**)&p_h1,  g_h1);
    cudaGetSymbolAddress((void**)&p_h2,  g_h2);
    cudaGetSymbolAddress((void**)&p_agg, g_agg);
    cudaGetSymbolAddress((void**)&p_z,   g_z);
    cudaGetSymbolAddress((void**)&p_M,   g_M);
    cudaGetSymbolAddress((void**)&p_h3,  g_h3);
    cudaGetSymbolAddress((void**)&p_S,   g_S);

    // prologue: gather x0 (+ zero agg, zero cnt); hist; scan; permute
    k_gather<<<NN * 32 / 256, 256>>>(emb, node_ids);
    k_hist<<<128, 512>>>(et);
    k_scan<<<1, 128>>>();
    k_permute<<<EE / PCH, PT>>>(et, src, dst, norm);

    // RGCN layer 0: h1 = relu(agg + b0 + x0 @ loop0); epilogue clears agg for layer 1
    k_edge<<<dim3(12, NRELC), 256>>>(p_x0, W0, p_agg);
    k_gemm_mma<<<dim3(64, 2), 256>>>(p_x0, loop0, p_h1, HH, p_agg, b0, 1, 1, nullptr);

    // RGCN layer 1: h2 = agg + b1 + h1 @ loop1
    k_edge<<<dim3(12, NRELC), 256>>>(p_h1, W1, p_agg);
    k_gemm_mma<<<dim3(64, 2), 256>>>(p_h1, loop1, p_h2, HH, p_agg, b1, 0, 0, nullptr);

    // VAE head fused: z = mean + exp(log_std)*eps
    k_gemm_z<<<dim3(64, 2), 256>>>(p_h2, Wz, bz, eps);

    // decode 1: h3 = z @ (z^T @ (z@Wi + bi + x0)) + hbi   [R@M == z(z^T M)]
    k_gemm_mma<<<dim3(64, 3), 256>>>(p_z, Wi, p_M, HH, p_x0, bi, 0, 0, p_S); // extra row zeroes S
    k_gemm_red_mma<<<64, 256>>>(p_z, p_M, p_S);
    k_gemm_mma<<<dim3(64, 2), 256>>>(p_z, p_S, p_h3, HH, nullptr, hbi, 0, 0, nullptr);

    // decode 2: out = h3 @ (h3^T @ (h3@Wo + bo + x0)) + hbo
    k_gemm_mma<<<dim3(64, 3), 256>>>(p_h3, Wo, p_M, HH, p_x0, bo, 0, 0, p_S);
    k_gemm_red_mma<<<64, 256>>>(p_h3, p_M, p_S);
    k_gemm_mma<<<dim3(64, 2), 256>>>(p_h3, p_S, out, HH, nullptr, hbo, 0, 0, nullptr);
}